// round 8
// baseline (speedup 1.0000x reference)
#include <cuda_runtime.h>
#include <math.h>

#define NMAX 20000
#define KNN 6
#define KCAND 7
#define NPARTK 6
#define NSUB 4
#define CTOT (NPARTK*NSUB*KCAND)   /* 168 candidates per node */
#define CSLICE (CTOT/8)            /* 21 per refine thread */
#define CMERGE 48                  /* 8 slices x 6 */

typedef unsigned int u32;

// ---------------- scratch (device globals; no allocation allowed) ----------------
__device__ __align__(16) float g_cnt [NMAX];
__device__ __align__(16) float g_agg1[NMAX*16];
__device__ __align__(16) float g_x1  [NMAX*16];
__device__ __align__(16) float g_sq1 [NMAX];
__device__ __align__(16) int   g_idx1[NMAX*KNN];
__device__ __align__(16) float g_y1  [NMAX*32];
__device__ __align__(16) float g_sq2 [NMAX];
__device__ __align__(16) float g_cat0[NMAX*48];
__device__ __align__(16) float g_agg2[NMAX*48];
__device__ __align__(16) int   g_idx2[NMAX*KNN];
__device__ __align__(16) float g_x3  [NMAX*64];
__device__ __align__(16) float g_y2  [NMAX*32];
__device__ __align__(16) float g_h1  [NMAX*96];
__device__ __align__(16) float g_cd  [NMAX*CTOT];
__device__ __align__(16) int   g_ci  [NMAX*CTOT];
__device__ __align__(16) float g_md  [NMAX*CMERGE];
__device__ __align__(16) int   g_mi  [NMAX*CMERGE];

#define MMA_TF32(c0,c1,c2,c3,a0,a1,a2,a3,b0,b1) \
    asm volatile("mma.sync.aligned.m16n8k8.row.col.f32.tf32.tf32.f32 " \
        "{%0,%1,%2,%3}, {%4,%5,%6,%7}, {%8,%9}, {%0,%1,%2,%3};" \
        : "+f"(c0), "+f"(c1), "+f"(c2), "+f"(c3) \
        : "r"(a0), "r"(a1), "r"(a2), "r"(a3), "r"(b0), "r"(b1))

// ---------------- init: agg1 = x (self loop), cnt = 1 ----------------
__global__ void init1_kernel(const float* __restrict__ x, int n){
    int t = blockIdx.x*blockDim.x + threadIdx.x;
    if (t < n*16) g_agg1[t] = x[t];
    if (t < n)    g_cnt[t]  = 1.0f;
}

// ---------------- scatter-add of x[src] into agg1[dst], count edges ----------------
__global__ void scatter1_kernel(const int* __restrict__ src, const int* __restrict__ dst,
                                const float* __restrict__ x, int E){
    int t = blockIdx.x*blockDim.x + threadIdx.x;
    int e = t >> 2;
    if (e >= E) return;
    int q = t & 3;
    int s = src[e], d = dst[e];
    if (q == 0) atomicAdd(&g_cnt[d], 1.0f);
    float4 v = reinterpret_cast<const float4*>(x)[s*4 + q];
    float* a = &g_agg1[d*16 + q*4];
    atomicAdd(a+0, v.x); atomicAdd(a+1, v.y); atomicAdd(a+2, v.z); atomicAdd(a+3, v.w);
}

// ---------------- feast: out = relu((agg/cnt) @ W + b), optional ||row||^2 ----------------
template<int IN, int OUT, bool WSQ>
__global__ void feast_kernel(const float* __restrict__ agg, const float* __restrict__ W,
                             const float* __restrict__ b, int n,
                             float* __restrict__ out, float* __restrict__ sqout){
    __shared__ float sW[IN*OUT];
    __shared__ float sb[OUT];
    for (int t = threadIdx.x; t < IN*OUT; t += blockDim.x) sW[t] = W[t];
    for (int t = threadIdx.x; t < OUT;    t += blockDim.x) sb[t] = b[t];
    __syncthreads();
    int i = blockIdx.x*blockDim.x + threadIdx.x;
    if (i >= n) return;
    float inv = 1.0f / g_cnt[i];
    float acc[OUT];
#pragma unroll
    for (int c = 0; c < OUT; c++) acc[c] = sb[c];
    for (int d = 0; d < IN; d++){
        float v = agg[i*IN+d] * inv;
#pragma unroll
        for (int c = 0; c < OUT; c++) acc[c] = fmaf(v, sW[d*OUT+c], acc[c]);
    }
    float sq = 0.f;
#pragma unroll
    for (int c = 0; c < OUT; c++){
        float r = fmaxf(acc[c], 0.f);
        out[i*OUT+c] = r;
        sq = fmaf(r, r, sq);
    }
    if (WSQ) sqout[i] = sq;
}

// ---------------- streaming top-7 insertion (approx keys) ----------------
__device__ __forceinline__ void upd7(float d, int j, float bd[KCAND], int bi[KCAND]){
    if (d < bd[KCAND-1]){
        bd[KCAND-1] = d; bi[KCAND-1] = j;
#pragma unroll
        for (int k = KCAND-1; k > 0; k--){
            if (bd[k] < bd[k-1]){
                float td = bd[k]; bd[k] = bd[k-1]; bd[k-1] = td;
                int   ti = bi[k]; bi[k] = bi[k-1]; bi[k-1] = ti;
            }
        }
    }
}

// ---------------- tensor-core kNN (single tf32 pass, fragment-layout smem) ----------------
// B rows staged pre-transposed so each thread's fragments are contiguous float4s:
// DIM=16: slot g*4+m <- element m*4+g  (1 x LDS.128/step, PAD=16 conflict-free)
// DIM=32: slot g*8+m <- element m*4+g  (2 x LDS.128/step, PAD=36 conflict-free)
// C initialized with sq_j so MMA output IS the approx distance.
// GROUP steps (32/16 j) share one min-tree + one rare gated insert per query.
template<int DIM, int PAD, int GROUP>
__global__ void __launch_bounds__(256)
knn_mma_kernel(const float* __restrict__ X, const float* __restrict__ sq,
               int n, int chunk){
    const int KC = DIM/8;
    const int Q4 = DIM/4;
    __shared__ float bs[128*PAD];
    __shared__ float sqs[128];

    int tid = threadIdx.x;
    int w = tid >> 5;
    int lane = tid & 31;
    int g = lane & 3;
    int rsub = lane >> 2;
    int qbase = blockIdx.x*128 + w*16;
    int r0 = qbase + rsub;
    int r1 = r0 + 8;
    int p = blockIdx.y;
    int jbeg = p * chunk;
    int jend = min(n, jbeg + chunk);

    int rr0 = min(r0, n-1), rr1 = min(r1, n-1);
    u32 a0[KC], a1[KC], a2[KC], a3[KC];
#pragma unroll
    for (int kc = 0; kc < KC; kc++){
        a0[kc] = __float_as_uint(-2.0f * X[rr0*DIM + kc*8 + g]);
        a1[kc] = __float_as_uint(-2.0f * X[rr1*DIM + kc*8 + g]);
        a2[kc] = __float_as_uint(-2.0f * X[rr0*DIM + kc*8 + g + 4]);
        a3[kc] = __float_as_uint(-2.0f * X[rr1*DIM + kc*8 + g + 4]);
    }

    float bdA[KCAND], bdB[KCAND]; int biA[KCAND], biB[KCAND];
#pragma unroll
    for (int k = 0; k < KCAND; k++){
        bdA[k] = INFINITY; biA[k] = -1;
        bdB[k] = INFINITY; biB[k] = -1;
    }

    for (int jt = jbeg; jt < jend; jt += 128){
        __syncthreads();
        // stage 128 j rows, transposed to fragment layout
        for (int idx = tid; idx < 128*Q4; idx += 256){
            int jr = idx / Q4;
            int q = idx % Q4;
            int gj = jt + jr;
            float4 v = {0.f,0.f,0.f,0.f};
            if (gj < jend) v = reinterpret_cast<const float4*>(X)[gj*Q4 + q];
            float* row = &bs[jr*PAD];
            const int M = Q4;       // slots per g-group (4 for DIM16, 8 for DIM32)
            row[0*M + q] = v.x;
            row[1*M + q] = v.y;
            row[2*M + q] = v.z;
            row[3*M + q] = v.w;
        }
        for (int idx = tid; idx < 128; idx += 256)
            sqs[idx] = (jt + idx < jend) ? sq[jt + idx] : INFINITY;
        __syncthreads();

#pragma unroll
        for (int jg = 0; jg < 128; jg += 8*GROUP){
            float cA[GROUP*2], cB[GROUP*2];
#pragma unroll
            for (int st = 0; st < GROUP; st++){
                int js = jg + st*8;
                float2 s2 = *reinterpret_cast<const float2*>(&sqs[js + 2*g]);
                float c0 = s2.x, c1 = s2.y, c2 = s2.x, c3 = s2.y;
                const float* row = &bs[(js + rsub)*PAD + g*Q4];
                if (DIM == 16){
                    float4 bf = *reinterpret_cast<const float4*>(row);
                    MMA_TF32(c0,c1,c2,c3, a0[0],a1[0],a2[0],a3[0],
                             __float_as_uint(bf.x), __float_as_uint(bf.y));
                    MMA_TF32(c0,c1,c2,c3, a0[KC-1],a1[KC-1],a2[KC-1],a3[KC-1],
                             __float_as_uint(bf.z), __float_as_uint(bf.w));
                } else {
                    float4 b1f = *reinterpret_cast<const float4*>(row);
                    float4 b2f = *reinterpret_cast<const float4*>(row + 4);
                    MMA_TF32(c0,c1,c2,c3, a0[0],a1[0],a2[0],a3[0],
                             __float_as_uint(b1f.x), __float_as_uint(b1f.y));
                    MMA_TF32(c0,c1,c2,c3, a0[1],a1[1],a2[1],a3[1],
                             __float_as_uint(b1f.z), __float_as_uint(b1f.w));
                    MMA_TF32(c0,c1,c2,c3, a0[KC-2],a1[KC-2],a2[KC-2],a3[KC-2],
                             __float_as_uint(b2f.x), __float_as_uint(b2f.y));
                    MMA_TF32(c0,c1,c2,c3, a0[KC-1],a1[KC-1],a2[KC-1],a3[KC-1],
                             __float_as_uint(b2f.z), __float_as_uint(b2f.w));
                }
                cA[st*2+0] = c0; cA[st*2+1] = c1;
                cB[st*2+0] = c2; cB[st*2+1] = c3;
            }
            int j0 = jt + jg + 2*g;

            float mA = cA[0];
#pragma unroll
            for (int v = 1; v < GROUP*2; v++) mA = fminf(mA, cA[v]);
            if (mA < bdA[KCAND-1]){
#pragma unroll
                for (int st = 0; st < GROUP; st++){
                    upd7(cA[st*2+0], j0 + st*8,     bdA, biA);
                    upd7(cA[st*2+1], j0 + st*8 + 1, bdA, biA);
                }
            }
            float mB = cB[0];
#pragma unroll
            for (int v = 1; v < GROUP*2; v++) mB = fminf(mB, cB[v]);
            if (mB < bdB[KCAND-1]){
#pragma unroll
                for (int st = 0; st < GROUP; st++){
                    upd7(cB[st*2+0], j0 + st*8,     bdB, biB);
                    upd7(cB[st*2+1], j0 + st*8 + 1, bdB, biB);
                }
            }
        }
    }
    if (r0 < n){
        int base = r0*CTOT + (p*NSUB + g)*KCAND;
#pragma unroll
        for (int k = 0; k < KCAND; k++){ g_cd[base+k] = bdA[k]; g_ci[base+k] = biA[k]; }
    }
    if (r1 < n){
        int base = r1*CTOT + (p*NSUB + g)*KCAND;
#pragma unroll
        for (int k = 0; k < KCAND; k++){ g_cd[base+k] = bdB[k]; g_ci[base+k] = biB[k]; }
    }
}

// ---------------- refine stage A: exact fp32 recompute, 8 threads/node ----------------
template<int DIM>
__global__ void refineA_kernel(const float* __restrict__ X, const float* __restrict__ sq,
                               int n){
    const int Q4 = DIM/4;
    int t = blockIdx.x*blockDim.x + threadIdx.x;
    int i = t >> 3;
    int s = t & 7;
    if (i >= n) return;
    float4 xi[Q4];
#pragma unroll
    for (int q = 0; q < Q4; q++) xi[q] = reinterpret_cast<const float4*>(X)[i*Q4 + q];

    float bd[KNN]; unsigned bi[KNN];
#pragma unroll
    for (int k = 0; k < KNN; k++){ bd[k] = INFINITY; bi[k] = 0xFFFFFFFFu; }

    int base = i*CTOT + s*CSLICE;
    for (int c = 0; c < CSLICE; c++){
        int jraw = g_ci[base+c];
        if (jraw < 0 || jraw == i) continue;
        unsigned j = (unsigned)jraw;
        float dot = 0.f;
#pragma unroll
        for (int q = 0; q < Q4; q++){
            float4 xj = reinterpret_cast<const float4*>(X)[jraw*Q4 + q];
            dot = fmaf(xi[q].x, xj.x, dot);
            dot = fmaf(xi[q].y, xj.y, dot);
            dot = fmaf(xi[q].z, xj.z, dot);
            dot = fmaf(xi[q].w, xj.w, dot);
        }
        float e = fmaf(-2.f, dot, sq[jraw]);
        if (e < bd[KNN-1] || (e == bd[KNN-1] && j < bi[KNN-1])){
            bd[KNN-1] = e; bi[KNN-1] = j;
#pragma unroll
            for (int k = KNN-1; k > 0; k--){
                bool sw = (bd[k] < bd[k-1]) || (bd[k] == bd[k-1] && bi[k] < bi[k-1]);
                if (sw){
                    float td = bd[k]; bd[k] = bd[k-1]; bd[k-1] = td;
                    unsigned ti = bi[k]; bi[k] = bi[k-1]; bi[k-1] = ti;
                }
            }
        }
    }
    int ob = i*CMERGE + s*KNN;
#pragma unroll
    for (int k = 0; k < KNN; k++){ g_md[ob+k] = bd[k]; g_mi[ob+k] = (int)bi[k]; }
}

// ---------------- refine stage B: merge 48 exact keys -> top-6 ----------------
__global__ void refineB_kernel(int n, int* __restrict__ outidx){
    int i = blockIdx.x*blockDim.x + threadIdx.x;
    if (i >= n) return;
    float bd[KNN]; unsigned bi[KNN];
#pragma unroll
    for (int k = 0; k < KNN; k++){ bd[k] = INFINITY; bi[k] = 0xFFFFFFFFu; }
    int base = i*CMERGE;
    for (int c = 0; c < CMERGE; c++){
        float d = g_md[base+c];
        unsigned j = (unsigned)g_mi[base+c];
        if (j == 0xFFFFFFFFu) continue;
        if (d < bd[KNN-1] || (d == bd[KNN-1] && j < bi[KNN-1])){
            bd[KNN-1] = d; bi[KNN-1] = j;
#pragma unroll
            for (int k = KNN-1; k > 0; k--){
                bool sw = (bd[k] < bd[k-1]) || (bd[k] == bd[k-1] && bi[k] < bi[k-1]);
                if (sw){
                    float td = bd[k]; bd[k] = bd[k-1]; bd[k-1] = td;
                    unsigned ti = bi[k]; bi[k] = bi[k-1]; bi[k-1] = ti;
                }
            }
        }
    }
#pragma unroll
    for (int k = 0; k < KNN; k++) outidx[i*KNN+k] = (int)bi[k];
}

// ---------------- dynamic edge conv ----------------
template<int F>
__global__ void edgeconv_kernel(const float* __restrict__ X, const int* __restrict__ idx,
                                const float* __restrict__ W1, const float* __restrict__ b1,
                                const float* __restrict__ W2, const float* __restrict__ b2,
                                int n, float* __restrict__ Y, float* __restrict__ sqout){
    __shared__ float sW1[2*F*32];
    __shared__ float sb1[32];
    __shared__ float sW2[32*32];
    __shared__ float sb2[32];
    for (int t = threadIdx.x; t < 2*F*32; t += blockDim.x) sW1[t] = W1[t];
    for (int t = threadIdx.x; t < 32*32;  t += blockDim.x) sW2[t] = W2[t];
    if (threadIdx.x < 32){ sb1[threadIdx.x] = b1[threadIdx.x]; sb2[threadIdx.x] = b2[threadIdx.x]; }
    __syncthreads();
    int i = blockIdx.x*blockDim.x + threadIdx.x;
    if (i >= n) return;

    float base[32];
#pragma unroll
    for (int c = 0; c < 32; c++) base[c] = sb1[c];
    for (int d = 0; d < F; d++){
        float v = X[i*F+d];
#pragma unroll
        for (int c = 0; c < 32; c++) base[c] = fmaf(v, sW1[d*32+c], base[c]);
    }
    float acc[32];
#pragma unroll
    for (int c = 0; c < 32; c++) acc[c] = -INFINITY;

    for (int kk = 0; kk < KNN; kk++){
        int j = idx[i*KNN+kk];
        float h[32];
#pragma unroll
        for (int c = 0; c < 32; c++) h[c] = base[c];
        for (int d = 0; d < F; d++){
            float v = X[j*F+d] - X[i*F+d];
#pragma unroll
            for (int c = 0; c < 32; c++) h[c] = fmaf(v, sW1[(F+d)*32+c], h[c]);
        }
#pragma unroll
        for (int c = 0; c < 32; c++) h[c] = fmaxf(h[c], 0.f);
#pragma unroll
        for (int c = 0; c < 32; c++){
            float o = sb2[c];
#pragma unroll
            for (int k = 0; k < 32; k++) o = fmaf(h[k], sW2[k*32+c], o);
            acc[c] = fmaxf(acc[c], o);
        }
    }
    float sqv = 0.f;
#pragma unroll
    for (int c = 0; c < 32; c++){
        float r = fmaxf(acc[c], 0.f);
        Y[i*32+c] = r;
        sqv = fmaf(r, r, sqv);
    }
    if (sqout) sqout[i] = sqv;
}

// ---------------- cat0 = [x1 | y1]; agg2 init = cat0 (self loop) ----------------
__global__ void cat0_kernel(int n){
    int t = blockIdx.x*blockDim.x + threadIdx.x;
    if (t >= n*48) return;
    int i = t / 48, d = t % 48;
    float v = (d < 16) ? g_x1[i*16+d] : g_y1[i*32 + (d-16)];
    g_cat0[t] = v;
    g_agg2[t] = v;
}

__global__ void scatter2_kernel(const int* __restrict__ src, const int* __restrict__ dst, int E){
    int t = blockIdx.x*blockDim.x + threadIdx.x;
    int e = t / 12;
    if (e >= E) return;
    int q = t % 12;
    int s = src[e], d = dst[e];
    float4 v = reinterpret_cast<const float4*>(g_cat0)[s*12 + q];
    float* a = &g_agg2[d*48 + q*4];
    atomicAdd(a+0, v.x); atomicAdd(a+1, v.y); atomicAdd(a+2, v.z); atomicAdd(a+3, v.w);
}

// ---------------- MLP layer 1 ----------------
__global__ void mlp1_kernel(const float* __restrict__ W, const float* __restrict__ b, int n){
    __shared__ float sW[96*96];
    __shared__ float sb[96];
    for (int t = threadIdx.x; t < 96*96; t += blockDim.x) sW[t] = W[t];
    for (int t = threadIdx.x; t < 96;    t += blockDim.x) sb[t] = b[t];
    __syncthreads();
    int i = blockIdx.x*blockDim.x + threadIdx.x;
    if (i >= n) return;
    float acc[96];
#pragma unroll
    for (int c = 0; c < 96; c++) acc[c] = sb[c];
    for (int d = 0; d < 64; d++){
        float v = g_x3[i*64+d];
#pragma unroll
        for (int c = 0; c < 96; c++) acc[c] = fmaf(v, sW[d*96+c], acc[c]);
    }
    for (int d = 0; d < 32; d++){
        float v = g_y2[i*32+d];
#pragma unroll
        for (int c = 0; c < 96; c++) acc[c] = fmaf(v, sW[(64+d)*96+c], acc[c]);
    }
#pragma unroll
    for (int c = 0; c < 96; c++) g_h1[i*96+c] = fmaxf(acc[c], 0.f);
}

// ---------------- MLP layers 2..out ----------------
__global__ void mlp2_kernel(const float* __restrict__ W2, const float* __restrict__ b2,
                            const float* __restrict__ W3, const float* __restrict__ b3,
                            const float* __restrict__ Wo, const float* __restrict__ bo,
                            int n, float* __restrict__ out){
    __shared__ float sW2[96*32]; __shared__ float sb2v[32];
    __shared__ float sW3[32*8];  __shared__ float sb3v[8];
    __shared__ float sWo[8];     __shared__ float sbo;
    for (int t = threadIdx.x; t < 96*32; t += blockDim.x) sW2[t] = W2[t];
    for (int t = threadIdx.x; t < 32*8;  t += blockDim.x) sW3[t] = W3[t];
    if (threadIdx.x < 32) sb2v[threadIdx.x] = b2[threadIdx.x];
    if (threadIdx.x < 8){ sb3v[threadIdx.x] = b3[threadIdx.x]; sWo[threadIdx.x] = Wo[threadIdx.x]; }
    if (threadIdx.x == 0) sbo = bo[0];
    __syncthreads();
    int i = blockIdx.x*blockDim.x + threadIdx.x;
    if (i >= n) return;
    float h[32];
#pragma unroll
    for (int c = 0; c < 32; c++) h[c] = sb2v[c];
    for (int d = 0; d < 96; d++){
        float v = g_h1[i*96+d];
#pragma unroll
        for (int c = 0; c < 32; c++) h[c] = fmaf(v, sW2[d*32+c], h[c]);
    }
#pragma unroll
    for (int c = 0; c < 32; c++) h[c] = fmaxf(h[c], 0.f);
    float g[8];
#pragma unroll
    for (int c = 0; c < 8; c++){
        float o = sb3v[c];
#pragma unroll
        for (int k = 0; k < 32; k++) o = fmaf(h[k], sW3[k*8+c], o);
        g[c] = fmaxf(o, 0.f);
    }
    float z = sbo;
#pragma unroll
    for (int c = 0; c < 8; c++) z = fmaf(g[c], sWo[c], z);
    out[i] = 1.0f / (1.0f + expf(-z));
}

// ---------------- launch ----------------
extern "C" void kernel_launch(void* const* d_in, const int* in_sizes, int n_in,
                              void* d_out, int out_size){
    const float* x   = (const float*)d_in[0];
    const int*   ei  = (const int*)  d_in[1];
    int n = in_sizes[0] / 16;
    int E = in_sizes[1] / 2;
    const int* src = ei;
    const int* dst = ei + E;

    const float* cW1 = (const float*)d_in[2];
    const float* cb1 = (const float*)d_in[5];
    const float* cW3 = (const float*)d_in[6];
    const float* cb3 = (const float*)d_in[9];
    const float* e1W1=(const float*)d_in[10]; const float* e1b1=(const float*)d_in[11];
    const float* e1W2=(const float*)d_in[12]; const float* e1b2=(const float*)d_in[13];
    const float* e2W1=(const float*)d_in[14]; const float* e2b1=(const float*)d_in[15];
    const float* e2W2=(const float*)d_in[16]; const float* e2b2=(const float*)d_in[17];
    const float* l1W =(const float*)d_in[18]; const float* l1b =(const float*)d_in[19];
    const float* l2W =(const float*)d_in[20]; const float* l2b =(const float*)d_in[21];
    const float* l3W =(const float*)d_in[22]; const float* l3b =(const float*)d_in[23];
    const float* oW  =(const float*)d_in[24]; const float* ob  =(const float*)d_in[25];
    float* out = (float*)d_out;

    void *p_agg1, *p_x1, *p_sq1, *p_idx1, *p_y1, *p_sq2, *p_agg2, *p_idx2, *p_x3, *p_y2;
    cudaGetSymbolAddress(&p_agg1, g_agg1);
    cudaGetSymbolAddress(&p_x1,   g_x1);
    cudaGetSymbolAddress(&p_sq1,  g_sq1);
    cudaGetSymbolAddress(&p_idx1, g_idx1);
    cudaGetSymbolAddress(&p_y1,   g_y1);
    cudaGetSymbolAddress(&p_sq2,  g_sq2);
    cudaGetSymbolAddress(&p_agg2, g_agg2);
    cudaGetSymbolAddress(&p_idx2, g_idx2);
    cudaGetSymbolAddress(&p_x3,   g_x3);
    cudaGetSymbolAddress(&p_y2,   g_y2);

    int nb = (n + 127) / 128;
    int chunk = (n + NPARTK - 1) / NPARTK;
    dim3 knngrid(nb, NPARTK);
    int refA = (n*8 + 127) / 128;

    // FeaSt 1 (heads=1 => attention == 1 => segment-mean then GEMM)
    init1_kernel<<<(n*16 + 255)/256, 256>>>(x, n);
    scatter1_kernel<<<(E*4 + 255)/256, 256>>>(src, dst, x, E);
    feast_kernel<16,16,true><<<nb,128>>>((const float*)p_agg1, cW1, cb1, n,
                                         (float*)p_x1, (float*)p_sq1);
    // kNN on x1 (dim 16): 1-pass tf32 MMA candidates + exact fp32 refine
    knn_mma_kernel<16,16,4><<<knngrid,256>>>((const float*)p_x1, (const float*)p_sq1, n, chunk);
    refineA_kernel<16><<<refA,128>>>((const float*)p_x1, (const float*)p_sq1, n);
    refineB_kernel<<<(n+255)/256,256>>>(n, (int*)p_idx1);
    edgeconv_kernel<16><<<nb,128>>>((const float*)p_x1, (const int*)p_idx1,
                                    e1W1, e1b1, e1W2, e1b2, n,
                                    (float*)p_y1, (float*)p_sq2);
    // FeaSt 2 on cat0 = [x1|y1]
    cat0_kernel<<<(n*48 + 255)/256, 256>>>(n);
    scatter2_kernel<<<(E*12 + 255)/256, 256>>>(src, dst, E);
    feast_kernel<48,64,false><<<nb,128>>>((const float*)p_agg2, cW3, cb3, n,
                                          (float*)p_x3, nullptr);
    // kNN on y1 (dim 32): 1-pass tf32 MMA candidates + exact fp32 refine
    knn_mma_kernel<32,36,2><<<knngrid,256>>>((const float*)p_y1, (const float*)p_sq2, n, chunk);
    refineA_kernel<32><<<refA,128>>>((const float*)p_y1, (const float*)p_sq2, n);
    refineB_kernel<<<(n+255)/256,256>>>(n, (int*)p_idx2);
    edgeconv_kernel<32><<<nb,128>>>((const float*)p_y1, (const int*)p_idx2,
                                    e2W1, e2b1, e2W2, e2b2, n,
                                    (float*)p_y2, nullptr);
    // Final MLP
    mlp1_kernel<<<nb,128>>>(l1W, l1b, n);
    mlp2_kernel<<<nb,128>>>(l2W, l2b, l3W, l3b, oW, ob, n, out);
}

// round 10
// speedup vs baseline: 1.2656x; 1.2656x over previous
#include <cuda_runtime.h>
#include <math.h>

#define NMAX 20000
#define KNN 6
#define KCAND 7
#define NPARTK 6
#define NSUB 4
#define CTOT (NPARTK*NSUB*KCAND)   /* 168 candidate slots per node */
#define CSLICE (CTOT/8)            /* 21 per refine thread */
#define CMERGE 48                  /* 8 slices x 6 */

typedef unsigned int u32;

// ---------------- scratch (device globals; no allocation allowed) ----------------
__device__ __align__(16) float g_cnt [NMAX];
__device__ __align__(16) float g_agg1[NMAX*16];
__device__ __align__(16) float g_x1  [NMAX*16];
__device__ __align__(16) float g_sq1 [NMAX];
__device__ __align__(16) int   g_idx1[NMAX*KNN];
__device__ __align__(16) float g_y1  [NMAX*32];
__device__ __align__(16) float g_sq2 [NMAX];
__device__ __align__(16) float g_cat0[NMAX*48];
__device__ __align__(16) float g_agg2[NMAX*48];
__device__ __align__(16) int   g_idx2[NMAX*KNN];
__device__ __align__(16) float g_x3  [NMAX*64];
__device__ __align__(16) float g_y2  [NMAX*32];
__device__ __align__(16) float g_h1  [NMAX*96];
__device__ __align__(16) int   g_ci  [NMAX*CTOT];
__device__ __align__(16) float g_md  [NMAX*CMERGE];
__device__ __align__(16) int   g_mi  [NMAX*CMERGE];

#define MMA_TF32(c0,c1,c2,c3,a0,a1,a2,a3,b0,b1) \
    asm volatile("mma.sync.aligned.m16n8k8.row.col.f32.tf32.tf32.f32 " \
        "{%0,%1,%2,%3}, {%4,%5,%6,%7}, {%8,%9}, {%0,%1,%2,%3};" \
        : "+f"(c0), "+f"(c1), "+f"(c2), "+f"(c3) \
        : "r"(a0), "r"(a1), "r"(a2), "r"(a3), "r"(b0), "r"(b1))

// monotone float -> u32 (order preserving), then splice j into low 15 bits
__device__ __forceinline__ u32 pack_key(float e, u32 j){
    u32 fb = __float_as_uint(e);
    u32 ord = fb ^ ((u32)((int)fb >> 31) | 0x80000000u);
    return (ord & 0xFFFF8000u) | j;
}

// branchless sorted insert of key into ascending 7-list (IMNMX only)
__device__ __forceinline__ void bubble7(u32 key, u32 r[KCAND]){
#pragma unroll
    for (int k = 0; k < KCAND; k++){
        u32 lo = umin(r[k], key);
        key    = umax(r[k], key);
        r[k] = lo;
    }
}

// ---------------- init: agg1 = x (self loop), cnt = 1 ----------------
__global__ void init1_kernel(const float* __restrict__ x, int n){
    int t = blockIdx.x*blockDim.x + threadIdx.x;
    if (t < n*16) g_agg1[t] = x[t];
    if (t < n)    g_cnt[t]  = 1.0f;
}

// ---------------- scatter-add of x[src] into agg1[dst], count edges ----------------
__global__ void scatter1_kernel(const int* __restrict__ src, const int* __restrict__ dst,
                                const float* __restrict__ x, int E){
    int t = blockIdx.x*blockDim.x + threadIdx.x;
    int e = t >> 2;
    if (e >= E) return;
    int q = t & 3;
    int s = src[e], d = dst[e];
    if (q == 0) atomicAdd(&g_cnt[d], 1.0f);
    float4 v = reinterpret_cast<const float4*>(x)[s*4 + q];
    float* a = &g_agg1[d*16 + q*4];
    atomicAdd(a+0, v.x); atomicAdd(a+1, v.y); atomicAdd(a+2, v.z); atomicAdd(a+3, v.w);
}

// ---------------- feast: out = relu((agg/cnt) @ W + b), optional ||row||^2 ----------------
template<int IN, int OUT, bool WSQ>
__global__ void feast_kernel(const float* __restrict__ agg, const float* __restrict__ W,
                             const float* __restrict__ b, int n,
                             float* __restrict__ out, float* __restrict__ sqout){
    __shared__ float sW[IN*OUT];
    __shared__ float sb[OUT];
    for (int t = threadIdx.x; t < IN*OUT; t += blockDim.x) sW[t] = W[t];
    for (int t = threadIdx.x; t < OUT;    t += blockDim.x) sb[t] = b[t];
    __syncthreads();
    int i = blockIdx.x*blockDim.x + threadIdx.x;
    if (i >= n) return;
    float inv = 1.0f / g_cnt[i];
    float acc[OUT];
#pragma unroll
    for (int c = 0; c < OUT; c++) acc[c] = sb[c];
    for (int d = 0; d < IN; d++){
        float v = agg[i*IN+d] * inv;
#pragma unroll
        for (int c = 0; c < OUT; c++) acc[c] = fmaf(v, sW[d*OUT+c], acc[c]);
    }
    float sq = 0.f;
#pragma unroll
    for (int c = 0; c < OUT; c++){
        float r = fmaxf(acc[c], 0.f);
        out[i*OUT+c] = r;
        sq = fmaf(r, r, sq);
    }
    if (WSQ) sqout[i] = sq;
}

// ---------------- tensor-core kNN (single tf32 pass, branchless key selection) ----------------
// B rows staged pre-transposed so each thread's fragments are contiguous float4s.
// DIM=16 PAD=16, DIM=32 PAD=36: both 16B-aligned (PAD%4==0) and LDS.128
// conflict-free (lane base addrs mod 32 = {0,4,...,28} per phase).
// C init = sq_j so MMA output IS the approx distance. Selection = packed u32 key
// bubbled through a 7-register ascending list with umin/umax: zero hot-loop branches.
template<int DIM, int PAD>
__global__ void __launch_bounds__(256)
knn_mma_kernel(const float* __restrict__ X, const float* __restrict__ sq,
               int n, int chunk){
    const int KC = DIM/8;
    const int Q4 = DIM/4;
    __shared__ float bs[128*PAD];
    __shared__ float sqs[128];

    int tid = threadIdx.x;
    int w = tid >> 5;
    int lane = tid & 31;
    int g = lane & 3;
    int rsub = lane >> 2;
    int qbase = blockIdx.x*128 + w*16;
    int r0 = qbase + rsub;
    int r1 = r0 + 8;
    int p = blockIdx.y;
    int jbeg = p * chunk;
    int jend = min(n, jbeg + chunk);

    int rr0 = min(r0, n-1), rr1 = min(r1, n-1);
    u32 a0[KC], a1[KC], a2[KC], a3[KC];
#pragma unroll
    for (int kc = 0; kc < KC; kc++){
        a0[kc] = __float_as_uint(-2.0f * X[rr0*DIM + kc*8 + g]);
        a1[kc] = __float_as_uint(-2.0f * X[rr1*DIM + kc*8 + g]);
        a2[kc] = __float_as_uint(-2.0f * X[rr0*DIM + kc*8 + g + 4]);
        a3[kc] = __float_as_uint(-2.0f * X[rr1*DIM + kc*8 + g + 4]);
    }

    u32 LA[KCAND], LB[KCAND];
#pragma unroll
    for (int k = 0; k < KCAND; k++){ LA[k] = 0xFFFFFFFFu; LB[k] = 0xFFFFFFFFu; }

    for (int jt = jbeg; jt < jend; jt += 128){
        __syncthreads();
        // stage 128 j rows, transposed to fragment layout
        for (int idx = tid; idx < 128*Q4; idx += 256){
            int jr = idx / Q4;
            int q = idx % Q4;
            int gj = jt + jr;
            float4 v = {0.f,0.f,0.f,0.f};
            if (gj < jend) v = reinterpret_cast<const float4*>(X)[gj*Q4 + q];
            float* row = &bs[jr*PAD];
            const int M = Q4;
            row[0*M + q] = v.x;
            row[1*M + q] = v.y;
            row[2*M + q] = v.z;
            row[3*M + q] = v.w;
        }
        for (int idx = tid; idx < 128; idx += 256)
            sqs[idx] = (jt + idx < jend) ? sq[jt + idx] : INFINITY;
        __syncthreads();

#pragma unroll 4
        for (int js = 0; js < 128; js += 8){
            float2 s2 = *reinterpret_cast<const float2*>(&sqs[js + 2*g]);
            float c0 = s2.x, c1 = s2.y, c2 = s2.x, c3 = s2.y;
            const float* row = &bs[(js + rsub)*PAD + g*Q4];
            if (DIM == 16){
                float4 bf = *reinterpret_cast<const float4*>(row);
                MMA_TF32(c0,c1,c2,c3, a0[0],a1[0],a2[0],a3[0],
                         __float_as_uint(bf.x), __float_as_uint(bf.y));
                MMA_TF32(c0,c1,c2,c3, a0[KC-1],a1[KC-1],a2[KC-1],a3[KC-1],
                         __float_as_uint(bf.z), __float_as_uint(bf.w));
            } else {
                float4 b1f = *reinterpret_cast<const float4*>(row);
                float4 b2f = *reinterpret_cast<const float4*>(row + 4);
                MMA_TF32(c0,c1,c2,c3, a0[0],a1[0],a2[0],a3[0],
                         __float_as_uint(b1f.x), __float_as_uint(b1f.y));
                MMA_TF32(c0,c1,c2,c3, a0[1],a1[1],a2[1],a3[1],
                         __float_as_uint(b1f.z), __float_as_uint(b1f.w));
                MMA_TF32(c0,c1,c2,c3, a0[KC-2],a1[KC-2],a2[KC-2],a3[KC-2],
                         __float_as_uint(b2f.x), __float_as_uint(b2f.y));
                MMA_TF32(c0,c1,c2,c3, a0[KC-1],a1[KC-1],a2[KC-1],a3[KC-1],
                         __float_as_uint(b2f.z), __float_as_uint(b2f.w));
            }
            u32 j0 = (u32)(jt + js + 2*g);
            bubble7(pack_key(c0, j0),   LA);
            bubble7(pack_key(c1, j0+1), LA);
            bubble7(pack_key(c2, j0),   LB);
            bubble7(pack_key(c3, j0+1), LB);
        }
    }
    if (r0 < n){
        int base = r0*CTOT + (p*NSUB + g)*KCAND;
#pragma unroll
        for (int k = 0; k < KCAND; k++) g_ci[base+k] = (int)(LA[k] & 0x7FFFu);
    }
    if (r1 < n){
        int base = r1*CTOT + (p*NSUB + g)*KCAND;
#pragma unroll
        for (int k = 0; k < KCAND; k++) g_ci[base+k] = (int)(LB[k] & 0x7FFFu);
    }
}

// ---------------- refine stage A: exact fp32 recompute, 8 threads/node ----------------
template<int DIM>
__global__ void refineA_kernel(const float* __restrict__ X, const float* __restrict__ sq,
                               int n){
    const int Q4 = DIM/4;
    int t = blockIdx.x*blockDim.x + threadIdx.x;
    int i = t >> 3;
    int s = t & 7;
    if (i >= n) return;
    float4 xi[Q4];
#pragma unroll
    for (int q = 0; q < Q4; q++) xi[q] = reinterpret_cast<const float4*>(X)[i*Q4 + q];

    float bd[KNN]; unsigned bi[KNN];
#pragma unroll
    for (int k = 0; k < KNN; k++){ bd[k] = INFINITY; bi[k] = 0xFFFFFFFFu; }

    int base = i*CTOT + s*CSLICE;
    for (int c = 0; c < CSLICE; c++){
        int jraw = g_ci[base+c];
        if (jraw >= n || jraw == i) continue;
        unsigned j = (unsigned)jraw;
        float dot = 0.f;
#pragma unroll
        for (int q = 0; q < Q4; q++){
            float4 xj = reinterpret_cast<const float4*>(X)[jraw*Q4 + q];
            dot = fmaf(xi[q].x, xj.x, dot);
            dot = fmaf(xi[q].y, xj.y, dot);
            dot = fmaf(xi[q].z, xj.z, dot);
            dot = fmaf(xi[q].w, xj.w, dot);
        }
        float e = fmaf(-2.f, dot, sq[jraw]);
        if (e < bd[KNN-1] || (e == bd[KNN-1] && j < bi[KNN-1])){
            bd[KNN-1] = e; bi[KNN-1] = j;
#pragma unroll
            for (int k = KNN-1; k > 0; k--){
                bool sw = (bd[k] < bd[k-1]) || (bd[k] == bd[k-1] && bi[k] < bi[k-1]);
                if (sw){
                    float td = bd[k]; bd[k] = bd[k-1]; bd[k-1] = td;
                    unsigned ti = bi[k]; bi[k] = bi[k-1]; bi[k-1] = ti;
                }
            }
        }
    }
    int ob = i*CMERGE + s*KNN;
#pragma unroll
    for (int k = 0; k < KNN; k++){ g_md[ob+k] = bd[k]; g_mi[ob+k] = (int)bi[k]; }
}

// ---------------- refine stage B: merge 48 exact keys -> top-6 ----------------
__global__ void refineB_kernel(int n, int* __restrict__ outidx){
    int i = blockIdx.x*blockDim.x + threadIdx.x;
    if (i >= n) return;
    float bd[KNN]; unsigned bi[KNN];
#pragma unroll
    for (int k = 0; k < KNN; k++){ bd[k] = INFINITY; bi[k] = 0xFFFFFFFFu; }
    int base = i*CMERGE;
    for (int c = 0; c < CMERGE; c++){
        float d = g_md[base+c];
        unsigned j = (unsigned)g_mi[base+c];
        if (j == 0xFFFFFFFFu) continue;
        if (d < bd[KNN-1] || (d == bd[KNN-1] && j < bi[KNN-1])){
            bd[KNN-1] = d; bi[KNN-1] = j;
#pragma unroll
            for (int k = KNN-1; k > 0; k--){
                bool sw = (bd[k] < bd[k-1]) || (bd[k] == bd[k-1] && bi[k] < bi[k-1]);
                if (sw){
                    float td = bd[k]; bd[k] = bd[k-1]; bd[k-1] = td;
                    unsigned ti = bi[k]; bi[k] = bi[k-1]; bi[k-1] = ti;
                }
            }
        }
    }
#pragma unroll
    for (int k = 0; k < KNN; k++) outidx[i*KNN+k] = (int)bi[k];
}

// ---------------- dynamic edge conv ----------------
template<int F>
__global__ void edgeconv_kernel(const float* __restrict__ X, const int* __restrict__ idx,
                                const float* __restrict__ W1, const float* __restrict__ b1,
                                const float* __restrict__ W2, const float* __restrict__ b2,
                                int n, float* __restrict__ Y, float* __restrict__ sqout){
    __shared__ float sW1[2*F*32];
    __shared__ float sb1[32];
    __shared__ float sW2[32*32];
    __shared__ float sb2[32];
    for (int t = threadIdx.x; t < 2*F*32; t += blockDim.x) sW1[t] = W1[t];
    for (int t = threadIdx.x; t < 32*32;  t += blockDim.x) sW2[t] = W2[t];
    if (threadIdx.x < 32){ sb1[threadIdx.x] = b1[threadIdx.x]; sb2[threadIdx.x] = b2[threadIdx.x]; }
    __syncthreads();
    int i = blockIdx.x*blockDim.x + threadIdx.x;
    if (i >= n) return;

    float base[32];
#pragma unroll
    for (int c = 0; c < 32; c++) base[c] = sb1[c];
    for (int d = 0; d < F; d++){
        float v = X[i*F+d];
#pragma unroll
        for (int c = 0; c < 32; c++) base[c] = fmaf(v, sW1[d*32+c], base[c]);
    }
    float acc[32];
#pragma unroll
    for (int c = 0; c < 32; c++) acc[c] = -INFINITY;

    for (int kk = 0; kk < KNN; kk++){
        int j = idx[i*KNN+kk];
        float h[32];
#pragma unroll
        for (int c = 0; c < 32; c++) h[c] = base[c];
        for (int d = 0; d < F; d++){
            float v = X[j*F+d] - X[i*F+d];
#pragma unroll
            for (int c = 0; c < 32; c++) h[c] = fmaf(v, sW1[(F+d)*32+c], h[c]);
        }
#pragma unroll
        for (int c = 0; c < 32; c++) h[c] = fmaxf(h[c], 0.f);
#pragma unroll
        for (int c = 0; c < 32; c++){
            float o = sb2[c];
#pragma unroll
            for (int k = 0; k < 32; k++) o = fmaf(h[k], sW2[k*32+c], o);
            acc[c] = fmaxf(acc[c], o);
        }
    }
    float sqv = 0.f;
#pragma unroll
    for (int c = 0; c < 32; c++){
        float r = fmaxf(acc[c], 0.f);
        Y[i*32+c] = r;
        sqv = fmaf(r, r, sqv);
    }
    if (sqout) sqout[i] = sqv;
}

// ---------------- cat0 = [x1 | y1]; agg2 init = cat0 (self loop) ----------------
__global__ void cat0_kernel(int n){
    int t = blockIdx.x*blockDim.x + threadIdx.x;
    if (t >= n*48) return;
    int i = t / 48, d = t % 48;
    float v = (d < 16) ? g_x1[i*16+d] : g_y1[i*32 + (d-16)];
    g_cat0[t] = v;
    g_agg2[t] = v;
}

__global__ void scatter2_kernel(const int* __restrict__ src, const int* __restrict__ dst, int E){
    int t = blockIdx.x*blockDim.x + threadIdx.x;
    int e = t / 12;
    if (e >= E) return;
    int q = t % 12;
    int s = src[e], d = dst[e];
    float4 v = reinterpret_cast<const float4*>(g_cat0)[s*12 + q];
    float* a = &g_agg2[d*48 + q*4];
    atomicAdd(a+0, v.x); atomicAdd(a+1, v.y); atomicAdd(a+2, v.z); atomicAdd(a+3, v.w);
}

// ---------------- MLP layer 1 ----------------
__global__ void mlp1_kernel(const float* __restrict__ W, const float* __restrict__ b, int n){
    __shared__ float sW[96*96];
    __shared__ float sb[96];
    for (int t = threadIdx.x; t < 96*96; t += blockDim.x) sW[t] = W[t];
    for (int t = threadIdx.x; t < 96;    t += blockDim.x) sb[t] = b[t];
    __syncthreads();
    int i = blockIdx.x*blockDim.x + threadIdx.x;
    if (i >= n) return;
    float acc[96];
#pragma unroll
    for (int c = 0; c < 96; c++) acc[c] = sb[c];
    for (int d = 0; d < 64; d++){
        float v = g_x3[i*64+d];
#pragma unroll
        for (int c = 0; c < 96; c++) acc[c] = fmaf(v, sW[d*96+c], acc[c]);
    }
    for (int d = 0; d < 32; d++){
        float v = g_y2[i*32+d];
#pragma unroll
        for (int c = 0; c < 96; c++) acc[c] = fmaf(v, sW[(64+d)*96+c], acc[c]);
    }
#pragma unroll
    for (int c = 0; c < 96; c++) g_h1[i*96+c] = fmaxf(acc[c], 0.f);
}

// ---------------- MLP layers 2..out ----------------
__global__ void mlp2_kernel(const float* __restrict__ W2, const float* __restrict__ b2,
                            const float* __restrict__ W3, const float* __restrict__ b3,
                            const float* __restrict__ Wo, const float* __restrict__ bo,
                            int n, float* __restrict__ out){
    __shared__ float sW2[96*32]; __shared__ float sb2v[32];
    __shared__ float sW3[32*8];  __shared__ float sb3v[8];
    __shared__ float sWo[8];     __shared__ float sbo;
    for (int t = threadIdx.x; t < 96*32; t += blockDim.x) sW2[t] = W2[t];
    for (int t = threadIdx.x; t < 32*8;  t += blockDim.x) sW3[t] = W3[t];
    if (threadIdx.x < 32) sb2v[threadIdx.x] = b2[threadIdx.x];
    if (threadIdx.x < 8){ sb3v[threadIdx.x] = b3[threadIdx.x]; sWo[threadIdx.x] = Wo[threadIdx.x]; }
    if (threadIdx.x == 0) sbo = bo[0];
    __syncthreads();
    int i = blockIdx.x*blockDim.x + threadIdx.x;
    if (i >= n) return;
    float h[32];
#pragma unroll
    for (int c = 0; c < 32; c++) h[c] = sb2v[c];
    for (int d = 0; d < 96; d++){
        float v = g_h1[i*96+d];
#pragma unroll
        for (int c = 0; c < 32; c++) h[c] = fmaf(v, sW2[d*32+c], h[c]);
    }
#pragma unroll
    for (int c = 0; c < 32; c++) h[c] = fmaxf(h[c], 0.f);
    float g[8];
#pragma unroll
    for (int c = 0; c < 8; c++){
        float o = sb3v[c];
#pragma unroll
        for (int k = 0; k < 32; k++) o = fmaf(h[k], sW3[k*8+c], o);
        g[c] = fmaxf(o, 0.f);
    }
    float z = sbo;
#pragma unroll
    for (int c = 0; c < 8; c++) z = fmaf(g[c], sWo[c], z);
    out[i] = 1.0f / (1.0f + expf(-z));
}

// ---------------- launch ----------------
extern "C" void kernel_launch(void* const* d_in, const int* in_sizes, int n_in,
                              void* d_out, int out_size){
    const float* x   = (const float*)d_in[0];
    const int*   ei  = (const int*)  d_in[1];
    int n = in_sizes[0] / 16;
    int E = in_sizes[1] / 2;
    const int* src = ei;
    const int* dst = ei + E;

    const float* cW1 = (const float*)d_in[2];
    const float* cb1 = (const float*)d_in[5];
    const float* cW3 = (const float*)d_in[6];
    const float* cb3 = (const float*)d_in[9];
    const float* e1W1=(const float*)d_in[10]; const float* e1b1=(const float*)d_in[11];
    const float* e1W2=(const float*)d_in[12]; const float* e1b2=(const float*)d_in[13];
    const float* e2W1=(const float*)d_in[14]; const float* e2b1=(const float*)d_in[15];
    const float* e2W2=(const float*)d_in[16]; const float* e2b2=(const float*)d_in[17];
    const float* l1W =(const float*)d_in[18]; const float* l1b =(const float*)d_in[19];
    const float* l2W =(const float*)d_in[20]; const float* l2b =(const float*)d_in[21];
    const float* l3W =(const float*)d_in[22]; const float* l3b =(const float*)d_in[23];
    const float* oW  =(const float*)d_in[24]; const float* ob  =(const float*)d_in[25];
    float* out = (float*)d_out;

    void *p_agg1, *p_x1, *p_sq1, *p_idx1, *p_y1, *p_sq2, *p_agg2, *p_idx2, *p_x3, *p_y2;
    cudaGetSymbolAddress(&p_agg1, g_agg1);
    cudaGetSymbolAddress(&p_x1,   g_x1);
    cudaGetSymbolAddress(&p_sq1,  g_sq1);
    cudaGetSymbolAddress(&p_idx1, g_idx1);
    cudaGetSymbolAddress(&p_y1,   g_y1);
    cudaGetSymbolAddress(&p_sq2,  g_sq2);
    cudaGetSymbolAddress(&p_agg2, g_agg2);
    cudaGetSymbolAddress(&p_idx2, g_idx2);
    cudaGetSymbolAddress(&p_x3,   g_x3);
    cudaGetSymbolAddress(&p_y2,   g_y2);

    int nb = (n + 127) / 128;
    int chunk = (n + NPARTK - 1) / NPARTK;
    dim3 knngrid(nb, NPARTK);
    int refA = (n*8 + 127) / 128;

    // FeaSt 1 (heads=1 => attention == 1 => segment-mean then GEMM)
    init1_kernel<<<(n*16 + 255)/256, 256>>>(x, n);
    scatter1_kernel<<<(E*4 + 255)/256, 256>>>(src, dst, x, E);
    feast_kernel<16,16,true><<<nb,128>>>((const float*)p_agg1, cW1, cb1, n,
                                         (float*)p_x1, (float*)p_sq1);
    // kNN on x1 (dim 16): 1-pass tf32 MMA + branchless key selection + exact refine
    knn_mma_kernel<16,16><<<knngrid,256>>>((const float*)p_x1, (const float*)p_sq1, n, chunk);
    refineA_kernel<16><<<refA,128>>>((const float*)p_x1, (const float*)p_sq1, n);
    refineB_kernel<<<(n+255)/256,256>>>(n, (int*)p_idx1);
    edgeconv_kernel<16><<<nb,128>>>((const float*)p_x1, (const int*)p_idx1,
                                    e1W1, e1b1, e1W2, e1b2, n,
                                    (float*)p_y1, (float*)p_sq2);
    // FeaSt 2 on cat0 = [x1|y1]
    cat0_kernel<<<(n*48 + 255)/256, 256>>>(n);
    scatter2_kernel<<<(E*12 + 255)/256, 256>>>(src, dst, E);
    feast_kernel<48,64,false><<<nb,128>>>((const float*)p_agg2, cW3, cb3, n,
                                          (float*)p_x3, nullptr);
    // kNN on y1 (dim 32): 1-pass tf32 MMA + branchless key selection + exact refine
    knn_mma_kernel<32,36><<<knngrid,256>>>((const float*)p_y1, (const float*)p_sq2, n, chunk);
    refineA_kernel<32><<<refA,128>>>((const float*)p_y1, (const float*)p_sq2, n);
    refineB_kernel<<<(n+255)/256,256>>>(n, (int*)p_idx2);
    edgeconv_kernel<32><<<nb,128>>>((const float*)p_y1, (const int*)p_idx2,
                                    e2W1, e2b1, e2W2, e2b2, n,
                                    (float*)p_y2, nullptr);
    // Final MLP
    mlp1_kernel<<<nb,128>>>(l1W, l1b, n);
    mlp2_kernel<<<nb,128>>>(l2W, l2b, l3W, l3b, oW, ob, n, out);
}

// round 11
// speedup vs baseline: 1.4658x; 1.1581x over previous
#include <cuda_runtime.h>
#include <math.h>

#define NMAX 20000
#define KNN 6
#define KCAND 6
#define NPARTK 6
#define NSUB 4
#define CTOT (NPARTK*NSUB*KCAND)   /* 144 candidate slots per node */
#define CSLICE (CTOT/8)            /* 18 per refine thread */
#define CMERGE 48                  /* 8 slices x 6 */

typedef unsigned int u32;

// ---------------- scratch (device globals; no allocation allowed) ----------------
__device__ __align__(16) float g_cnt [NMAX];
__device__ __align__(16) float g_agg1[NMAX*16];
__device__ __align__(16) float g_x1  [NMAX*16];
__device__ __align__(16) float g_sq1 [NMAX];
__device__ __align__(16) int   g_idx1[NMAX*KNN];
__device__ __align__(16) float g_y1  [NMAX*32];
__device__ __align__(16) float g_sq2 [NMAX];
__device__ __align__(16) float g_cat0[NMAX*48];
__device__ __align__(16) float g_agg2[NMAX*48];
__device__ __align__(16) int   g_idx2[NMAX*KNN];
__device__ __align__(16) float g_x3  [NMAX*64];
__device__ __align__(16) float g_y2  [NMAX*32];
__device__ __align__(16) float g_h1  [NMAX*96];
__device__ __align__(16) int   g_ci  [NMAX*CTOT];
__device__ __align__(16) float g_md  [NMAX*CMERGE];
__device__ __align__(16) int   g_mi  [NMAX*CMERGE];

#define MMA_TF32(c0,c1,c2,c3,a0,a1,a2,a3,b0,b1) \
    asm volatile("mma.sync.aligned.m16n8k8.row.col.f32.tf32.tf32.f32 " \
        "{%0,%1,%2,%3}, {%4,%5,%6,%7}, {%8,%9}, {%0,%1,%2,%3};" \
        : "+f"(c0), "+f"(c1), "+f"(c2), "+f"(c3) \
        : "r"(a0), "r"(a1), "r"(a2), "r"(a3), "r"(b0), "r"(b1))

// float key: truncate distance mantissa to 17 high bits, splice j into low 15.
// IEEE float compare (FMNMX) gives correct distance order for any signs;
// FMNMX returns an operand verbatim, so the j-field survives selection.
__device__ __forceinline__ float fpack(float e, u32 j){
    return __uint_as_float((__float_as_uint(e) & 0xFFFF8000u) | j);
}

// branchless sorted insert into ascending 6-list (FMNMX only, alu pipe)
__device__ __forceinline__ void fbubble(float key, float r[KCAND]){
#pragma unroll
    for (int k = 0; k < KCAND; k++){
        float lo = fminf(r[k], key);
        key      = fmaxf(r[k], key);
        r[k] = lo;
    }
}

// init key: FLT_MAX bit pattern => j-field = 0x7FFF (>= n, skipped by refine)
#define KEY_INIT __uint_as_float(0x7F7FFFFFu)

// ---------------- init: agg1 = x (self loop), cnt = 1 ----------------
__global__ void init1_kernel(const float* __restrict__ x, int n){
    int t = blockIdx.x*blockDim.x + threadIdx.x;
    if (t < n*16) g_agg1[t] = x[t];
    if (t < n)    g_cnt[t]  = 1.0f;
}

// ---------------- scatter-add of x[src] into agg1[dst], count edges ----------------
__global__ void scatter1_kernel(const int* __restrict__ src, const int* __restrict__ dst,
                                const float* __restrict__ x, int E){
    int t = blockIdx.x*blockDim.x + threadIdx.x;
    int e = t >> 2;
    if (e >= E) return;
    int q = t & 3;
    int s = src[e], d = dst[e];
    if (q == 0) atomicAdd(&g_cnt[d], 1.0f);
    float4 v = reinterpret_cast<const float4*>(x)[s*4 + q];
    float* a = &g_agg1[d*16 + q*4];
    atomicAdd(a+0, v.x); atomicAdd(a+1, v.y); atomicAdd(a+2, v.z); atomicAdd(a+3, v.w);
}

// ---------------- feast: out = relu((agg/cnt) @ W + b), optional ||row||^2 ----------------
template<int IN, int OUT, bool WSQ>
__global__ void feast_kernel(const float* __restrict__ agg, const float* __restrict__ W,
                             const float* __restrict__ b, int n,
                             float* __restrict__ out, float* __restrict__ sqout){
    __shared__ float sW[IN*OUT];
    __shared__ float sb[OUT];
    for (int t = threadIdx.x; t < IN*OUT; t += blockDim.x) sW[t] = W[t];
    for (int t = threadIdx.x; t < OUT;    t += blockDim.x) sb[t] = b[t];
    __syncthreads();
    int i = blockIdx.x*blockDim.x + threadIdx.x;
    if (i >= n) return;
    float inv = 1.0f / g_cnt[i];
    float acc[OUT];
#pragma unroll
    for (int c = 0; c < OUT; c++) acc[c] = sb[c];
    for (int d = 0; d < IN; d++){
        float v = agg[i*IN+d] * inv;
#pragma unroll
        for (int c = 0; c < OUT; c++) acc[c] = fmaf(v, sW[d*OUT+c], acc[c]);
    }
    float sq = 0.f;
#pragma unroll
    for (int c = 0; c < OUT; c++){
        float r = fmaxf(acc[c], 0.f);
        out[i*OUT+c] = r;
        sq = fmaf(r, r, sq);
    }
    if (WSQ) sqout[i] = sq;
}

// ---------------- tensor-core kNN (single tf32 pass, branchless float-key selection) ----------------
// B rows staged pre-transposed so each thread's fragments are contiguous float4s.
// DIM=16 PAD=16, DIM=32 PAD=36: 16B-aligned and LDS.128 conflict-free.
// C init = sq_j so MMA output IS the approx distance. Selection = float key
// (dist|j) bubbled through a 6-register ascending list with fminf/fmaxf.
template<int DIM, int PAD>
__global__ void __launch_bounds__(256)
knn_mma_kernel(const float* __restrict__ X, const float* __restrict__ sq,
               int n, int chunk){
    const int KC = DIM/8;
    const int Q4 = DIM/4;
    __shared__ float bs[128*PAD];
    __shared__ float sqs[128];

    int tid = threadIdx.x;
    int w = tid >> 5;
    int lane = tid & 31;
    int g = lane & 3;
    int rsub = lane >> 2;
    int qbase = blockIdx.x*128 + w*16;
    int r0 = qbase + rsub;
    int r1 = r0 + 8;
    int p = blockIdx.y;
    int jbeg = p * chunk;
    int jend = min(n, jbeg + chunk);

    int rr0 = min(r0, n-1), rr1 = min(r1, n-1);
    u32 a0[KC], a1[KC], a2[KC], a3[KC];
#pragma unroll
    for (int kc = 0; kc < KC; kc++){
        a0[kc] = __float_as_uint(-2.0f * X[rr0*DIM + kc*8 + g]);
        a1[kc] = __float_as_uint(-2.0f * X[rr1*DIM + kc*8 + g]);
        a2[kc] = __float_as_uint(-2.0f * X[rr0*DIM + kc*8 + g + 4]);
        a3[kc] = __float_as_uint(-2.0f * X[rr1*DIM + kc*8 + g + 4]);
    }

    float LA[KCAND], LB[KCAND];
#pragma unroll
    for (int k = 0; k < KCAND; k++){ LA[k] = KEY_INIT; LB[k] = KEY_INIT; }

    for (int jt = jbeg; jt < jend; jt += 128){
        __syncthreads();
        // stage 128 j rows, transposed to fragment layout
        for (int idx = tid; idx < 128*Q4; idx += 256){
            int jr = idx / Q4;
            int q = idx % Q4;
            int gj = jt + jr;
            float4 v = {0.f,0.f,0.f,0.f};
            if (gj < jend) v = reinterpret_cast<const float4*>(X)[gj*Q4 + q];
            float* row = &bs[jr*PAD];
            const int M = Q4;
            row[0*M + q] = v.x;
            row[1*M + q] = v.y;
            row[2*M + q] = v.z;
            row[3*M + q] = v.w;
        }
        for (int idx = tid; idx < 128; idx += 256)
            sqs[idx] = (jt + idx < jend) ? sq[jt + idx] : 1e30f;  // finite pad (no NaN keys)
        __syncthreads();

#pragma unroll
        for (int js = 0; js < 128; js += 8){
            float2 s2 = *reinterpret_cast<const float2*>(&sqs[js + 2*g]);
            float c0 = s2.x, c1 = s2.y, c2 = s2.x, c3 = s2.y;
            const float* row = &bs[(js + rsub)*PAD + g*Q4];
            if (DIM == 16){
                float4 bf = *reinterpret_cast<const float4*>(row);
                MMA_TF32(c0,c1,c2,c3, a0[0],a1[0],a2[0],a3[0],
                         __float_as_uint(bf.x), __float_as_uint(bf.y));
                MMA_TF32(c0,c1,c2,c3, a0[KC-1],a1[KC-1],a2[KC-1],a3[KC-1],
                         __float_as_uint(bf.z), __float_as_uint(bf.w));
            } else {
                float4 b1f = *reinterpret_cast<const float4*>(row);
                float4 b2f = *reinterpret_cast<const float4*>(row + 4);
                MMA_TF32(c0,c1,c2,c3, a0[0],a1[0],a2[0],a3[0],
                         __float_as_uint(b1f.x), __float_as_uint(b1f.y));
                MMA_TF32(c0,c1,c2,c3, a0[1],a1[1],a2[1],a3[1],
                         __float_as_uint(b1f.z), __float_as_uint(b1f.w));
                MMA_TF32(c0,c1,c2,c3, a0[KC-2],a1[KC-2],a2[KC-2],a3[KC-2],
                         __float_as_uint(b2f.x), __float_as_uint(b2f.y));
                MMA_TF32(c0,c1,c2,c3, a0[KC-1],a1[KC-1],a2[KC-1],a3[KC-1],
                         __float_as_uint(b2f.z), __float_as_uint(b2f.w));
            }
            u32 j0 = (u32)(jt + js + 2*g);
            fbubble(fpack(c0, j0),   LA);
            fbubble(fpack(c1, j0+1), LA);
            fbubble(fpack(c2, j0),   LB);
            fbubble(fpack(c3, j0+1), LB);
        }
    }
    if (r0 < n){
        int base = r0*CTOT + (p*NSUB + g)*KCAND;
#pragma unroll
        for (int k = 0; k < KCAND; k++) g_ci[base+k] = (int)(__float_as_uint(LA[k]) & 0x7FFFu);
    }
    if (r1 < n){
        int base = r1*CTOT + (p*NSUB + g)*KCAND;
#pragma unroll
        for (int k = 0; k < KCAND; k++) g_ci[base+k] = (int)(__float_as_uint(LB[k]) & 0x7FFFu);
    }
}

// ---------------- refine stage A: exact fp32 recompute, 8 threads/node ----------------
template<int DIM>
__global__ void refineA_kernel(const float* __restrict__ X, const float* __restrict__ sq,
                               int n){
    const int Q4 = DIM/4;
    int t = blockIdx.x*blockDim.x + threadIdx.x;
    int i = t >> 3;
    int s = t & 7;
    if (i >= n) return;
    float4 xi[Q4];
#pragma unroll
    for (int q = 0; q < Q4; q++) xi[q] = reinterpret_cast<const float4*>(X)[i*Q4 + q];

    float bd[KNN]; unsigned bi[KNN];
#pragma unroll
    for (int k = 0; k < KNN; k++){ bd[k] = INFINITY; bi[k] = 0xFFFFFFFFu; }

    int base = i*CTOT + s*CSLICE;
    for (int c = 0; c < CSLICE; c++){
        int jraw = g_ci[base+c];
        if (jraw >= n || jraw == i) continue;
        unsigned j = (unsigned)jraw;
        float dot = 0.f;
#pragma unroll
        for (int q = 0; q < Q4; q++){
            float4 xj = reinterpret_cast<const float4*>(X)[jraw*Q4 + q];
            dot = fmaf(xi[q].x, xj.x, dot);
            dot = fmaf(xi[q].y, xj.y, dot);
            dot = fmaf(xi[q].z, xj.z, dot);
            dot = fmaf(xi[q].w, xj.w, dot);
        }
        float e = fmaf(-2.f, dot, sq[jraw]);
        if (e < bd[KNN-1] || (e == bd[KNN-1] && j < bi[KNN-1])){
            bd[KNN-1] = e; bi[KNN-1] = j;
#pragma unroll
            for (int k = KNN-1; k > 0; k--){
                bool sw = (bd[k] < bd[k-1]) || (bd[k] == bd[k-1] && bi[k] < bi[k-1]);
                if (sw){
                    float td = bd[k]; bd[k] = bd[k-1]; bd[k-1] = td;
                    unsigned ti = bi[k]; bi[k] = bi[k-1]; bi[k-1] = ti;
                }
            }
        }
    }
    int ob = i*CMERGE + s*KNN;
#pragma unroll
    for (int k = 0; k < KNN; k++){ g_md[ob+k] = bd[k]; g_mi[ob+k] = (int)bi[k]; }
}

// ---------------- refine stage B: merge 48 exact keys -> top-6 ----------------
__global__ void refineB_kernel(int n, int* __restrict__ outidx){
    int i = blockIdx.x*blockDim.x + threadIdx.x;
    if (i >= n) return;
    float bd[KNN]; unsigned bi[KNN];
#pragma unroll
    for (int k = 0; k < KNN; k++){ bd[k] = INFINITY; bi[k] = 0xFFFFFFFFu; }
    int base = i*CMERGE;
    for (int c = 0; c < CMERGE; c++){
        float d = g_md[base+c];
        unsigned j = (unsigned)g_mi[base+c];
        if (j == 0xFFFFFFFFu) continue;
        if (d < bd[KNN-1] || (d == bd[KNN-1] && j < bi[KNN-1])){
            bd[KNN-1] = d; bi[KNN-1] = j;
#pragma unroll
            for (int k = KNN-1; k > 0; k--){
                bool sw = (bd[k] < bd[k-1]) || (bd[k] == bd[k-1] && bi[k] < bi[k-1]);
                if (sw){
                    float td = bd[k]; bd[k] = bd[k-1]; bd[k-1] = td;
                    unsigned ti = bi[k]; bi[k] = bi[k-1]; bi[k-1] = ti;
                }
            }
        }
    }
#pragma unroll
    for (int k = 0; k < KNN; k++) outidx[i*KNN+k] = (int)bi[k];
}

// ---------------- dynamic edge conv ----------------
template<int F>
__global__ void edgeconv_kernel(const float* __restrict__ X, const int* __restrict__ idx,
                                const float* __restrict__ W1, const float* __restrict__ b1,
                                const float* __restrict__ W2, const float* __restrict__ b2,
                                int n, float* __restrict__ Y, float* __restrict__ sqout){
    __shared__ float sW1[2*F*32];
    __shared__ float sb1[32];
    __shared__ float sW2[32*32];
    __shared__ float sb2[32];
    for (int t = threadIdx.x; t < 2*F*32; t += blockDim.x) sW1[t] = W1[t];
    for (int t = threadIdx.x; t < 32*32;  t += blockDim.x) sW2[t] = W2[t];
    if (threadIdx.x < 32){ sb1[threadIdx.x] = b1[threadIdx.x]; sb2[threadIdx.x] = b2[threadIdx.x]; }
    __syncthreads();
    int i = blockIdx.x*blockDim.x + threadIdx.x;
    if (i >= n) return;

    float base[32];
#pragma unroll
    for (int c = 0; c < 32; c++) base[c] = sb1[c];
    for (int d = 0; d < F; d++){
        float v = X[i*F+d];
#pragma unroll
        for (int c = 0; c < 32; c++) base[c] = fmaf(v, sW1[d*32+c], base[c]);
    }
    float acc[32];
#pragma unroll
    for (int c = 0; c < 32; c++) acc[c] = -INFINITY;

    for (int kk = 0; kk < KNN; kk++){
        int j = idx[i*KNN+kk];
        float h[32];
#pragma unroll
        for (int c = 0; c < 32; c++) h[c] = base[c];
        for (int d = 0; d < F; d++){
            float v = X[j*F+d] - X[i*F+d];
#pragma unroll
            for (int c = 0; c < 32; c++) h[c] = fmaf(v, sW1[(F+d)*32+c], h[c]);
        }
#pragma unroll
        for (int c = 0; c < 32; c++) h[c] = fmaxf(h[c], 0.f);
#pragma unroll
        for (int c = 0; c < 32; c++){
            float o = sb2[c];
#pragma unroll
            for (int k = 0; k < 32; k++) o = fmaf(h[k], sW2[k*32+c], o);
            acc[c] = fmaxf(acc[c], o);
        }
    }
    float sqv = 0.f;
#pragma unroll
    for (int c = 0; c < 32; c++){
        float r = fmaxf(acc[c], 0.f);
        Y[i*32+c] = r;
        sqv = fmaf(r, r, sqv);
    }
    if (sqout) sqout[i] = sqv;
}

// ---------------- cat0 = [x1 | y1]; agg2 init = cat0 (self loop) ----------------
__global__ void cat0_kernel(int n){
    int t = blockIdx.x*blockDim.x + threadIdx.x;
    if (t >= n*48) return;
    int i = t / 48, d = t % 48;
    float v = (d < 16) ? g_x1[i*16+d] : g_y1[i*32 + (d-16)];
    g_cat0[t] = v;
    g_agg2[t] = v;
}

__global__ void scatter2_kernel(const int* __restrict__ src, const int* __restrict__ dst, int E){
    int t = blockIdx.x*blockDim.x + threadIdx.x;
    int e = t / 12;
    if (e >= E) return;
    int q = t % 12;
    int s = src[e], d = dst[e];
    float4 v = reinterpret_cast<const float4*>(g_cat0)[s*12 + q];
    float* a = &g_agg2[d*48 + q*4];
    atomicAdd(a+0, v.x); atomicAdd(a+1, v.y); atomicAdd(a+2, v.z); atomicAdd(a+3, v.w);
}

// ---------------- MLP layer 1 ----------------
__global__ void mlp1_kernel(const float* __restrict__ W, const float* __restrict__ b, int n){
    __shared__ float sW[96*96];
    __shared__ float sb[96];
    for (int t = threadIdx.x; t < 96*96; t += blockDim.x) sW[t] = W[t];
    for (int t = threadIdx.x; t < 96;    t += blockDim.x) sb[t] = b[t];
    __syncthreads();
    int i = blockIdx.x*blockDim.x + threadIdx.x;
    if (i >= n) return;
    float acc[96];
#pragma unroll
    for (int c = 0; c < 96; c++) acc[c] = sb[c];
    for (int d = 0; d < 64; d++){
        float v = g_x3[i*64+d];
#pragma unroll
        for (int c = 0; c < 96; c++) acc[c] = fmaf(v, sW[d*96+c], acc[c]);
    }
    for (int d = 0; d < 32; d++){
        float v = g_y2[i*32+d];
#pragma unroll
        for (int c = 0; c < 96; c++) acc[c] = fmaf(v, sW[(64+d)*96+c], acc[c]);
    }
#pragma unroll
    for (int c = 0; c < 96; c++) g_h1[i*96+c] = fmaxf(acc[c], 0.f);
}

// ---------------- MLP layers 2..out ----------------
__global__ void mlp2_kernel(const float* __restrict__ W2, const float* __restrict__ b2,
                            const float* __restrict__ W3, const float* __restrict__ b3,
                            const float* __restrict__ Wo, const float* __restrict__ bo,
                            int n, float* __restrict__ out){
    __shared__ float sW2[96*32]; __shared__ float sb2v[32];
    __shared__ float sW3[32*8];  __shared__ float sb3v[8];
    __shared__ float sWo[8];     __shared__ float sbo;
    for (int t = threadIdx.x; t < 96*32; t += blockDim.x) sW2[t] = W2[t];
    for (int t = threadIdx.x; t < 32*8;  t += blockDim.x) sW3[t] = W3[t];
    if (threadIdx.x < 32) sb2v[threadIdx.x] = b2[threadIdx.x];
    if (threadIdx.x < 8){ sb3v[threadIdx.x] = b3[threadIdx.x]; sWo[threadIdx.x] = Wo[threadIdx.x]; }
    if (threadIdx.x == 0) sbo = bo[0];
    __syncthreads();
    int i = blockIdx.x*blockDim.x + threadIdx.x;
    if (i >= n) return;
    float h[32];
#pragma unroll
    for (int c = 0; c < 32; c++) h[c] = sb2v[c];
    for (int d = 0; d < 96; d++){
        float v = g_h1[i*96+d];
#pragma unroll
        for (int c = 0; c < 32; c++) h[c] = fmaf(v, sW2[d*32+c], h[c]);
    }
#pragma unroll
    for (int c = 0; c < 32; c++) h[c] = fmaxf(h[c], 0.f);
    float g[8];
#pragma unroll
    for (int c = 0; c < 8; c++){
        float o = sb3v[c];
#pragma unroll
        for (int k = 0; k < 32; k++) o = fmaf(h[k], sW3[k*8+c], o);
        g[c] = fmaxf(o, 0.f);
    }
    float z = sbo;
#pragma unroll
    for (int c = 0; c < 8; c++) z = fmaf(g[c], sWo[c], z);
    out[i] = 1.0f / (1.0f + expf(-z));
}

// ---------------- launch ----------------
extern "C" void kernel_launch(void* const* d_in, const int* in_sizes, int n_in,
                              void* d_out, int out_size){
    const float* x   = (const float*)d_in[0];
    const int*   ei  = (const int*)  d_in[1];
    int n = in_sizes[0] / 16;
    int E = in_sizes[1] / 2;
    const int* src = ei;
    const int* dst = ei + E;

    const float* cW1 = (const float*)d_in[2];
    const float* cb1 = (const float*)d_in[5];
    const float* cW3 = (const float*)d_in[6];
    const float* cb3 = (const float*)d_in[9];
    const float* e1W1=(const float*)d_in[10]; const float* e1b1=(const float*)d_in[11];
    const float* e1W2=(const float*)d_in[12]; const float* e1b2=(const float*)d_in[13];
    const float* e2W1=(const float*)d_in[14]; const float* e2b1=(const float*)d_in[15];
    const float* e2W2=(const float*)d_in[16]; const float* e2b2=(const float*)d_in[17];
    const float* l1W =(const float*)d_in[18]; const float* l1b =(const float*)d_in[19];
    const float* l2W =(const float*)d_in[20]; const float* l2b =(const float*)d_in[21];
    const float* l3W =(const float*)d_in[22]; const float* l3b =(const float*)d_in[23];
    const float* oW  =(const float*)d_in[24]; const float* ob  =(const float*)d_in[25];
    float* out = (float*)d_out;

    void *p_agg1, *p_x1, *p_sq1, *p_idx1, *p_y1, *p_sq2, *p_agg2, *p_idx2, *p_x3, *p_y2;
    cudaGetSymbolAddress(&p_agg1, g_agg1);
    cudaGetSymbolAddress(&p_x1,   g_x1);
    cudaGetSymbolAddress(&p_sq1,  g_sq1);
    cudaGetSymbolAddress(&p_idx1, g_idx1);
    cudaGetSymbolAddress(&p_y1,   g_y1);
    cudaGetSymbolAddress(&p_sq2,  g_sq2);
    cudaGetSymbolAddress(&p_agg2, g_agg2);
    cudaGetSymbolAddress(&p_idx2, g_idx2);
    cudaGetSymbolAddress(&p_x3,   g_x3);
    cudaGetSymbolAddress(&p_y2,   g_y2);

    int nb = (n + 127) / 128;
    int chunk = (n + NPARTK - 1) / NPARTK;
    dim3 knngrid(nb, NPARTK);
    int refA = (n*8 + 127) / 128;

    // FeaSt 1 (heads=1 => attention == 1 => segment-mean then GEMM)
    init1_kernel<<<(n*16 + 255)/256, 256>>>(x, n);
    scatter1_kernel<<<(E*4 + 255)/256, 256>>>(src, dst, x, E);
    feast_kernel<16,16,true><<<nb,128>>>((const float*)p_agg1, cW1, cb1, n,
                                         (float*)p_x1, (float*)p_sq1);
    // kNN on x1 (dim 16): 1-pass tf32 MMA + branchless float-key selection + exact refine
    knn_mma_kernel<16,16><<<knngrid,256>>>((const float*)p_x1, (const float*)p_sq1, n, chunk);
    refineA_kernel<16><<<refA,128>>>((const float*)p_x1, (const float*)p_sq1, n);
    refineB_kernel<<<(n+255)/256,256>>>(n, (int*)p_idx1);
    edgeconv_kernel<16><<<nb,128>>>((const float*)p_x1, (const int*)p_idx1,
                                    e1W1, e1b1, e1W2, e1b2, n,
                                    (float*)p_y1, (float*)p_sq2);
    // FeaSt 2 on cat0 = [x1|y1]
    cat0_kernel<<<(n*48 + 255)/256, 256>>>(n);
    scatter2_kernel<<<(E*12 + 255)/256, 256>>>(src, dst, E);
    feast_kernel<48,64,false><<<nb,128>>>((const float*)p_agg2, cW3, cb3, n,
                                          (float*)p_x3, nullptr);
    // kNN on y1 (dim 32): 1-pass tf32 MMA + branchless float-key selection + exact refine
    knn_mma_kernel<32,36><<<knngrid,256>>>((const float*)p_y1, (const float*)p_sq2, n, chunk);
    refineA_kernel<32><<<refA,128>>>((const float*)p_y1, (const float*)p_sq2, n);
    refineB_kernel<<<(n+255)/256,256>>>(n, (int*)p_idx2);
    edgeconv_kernel<32><<<nb,128>>>((const float*)p_y1, (const int*)p_idx2,
                                    e2W1, e2b1, e2W2, e2b2, n,
                                    (float*)p_y2, nullptr);
    // Final MLP
    mlp1_kernel<<<nb,128>>>(l1W, l1b, n);
    mlp2_kernel<<<nb,128>>>(l2W, l2b, l3W, l3b, oW, ob, n, out);
}

// round 12
// speedup vs baseline: 1.6015x; 1.0926x over previous
#include <cuda_runtime.h>
#include <math.h>

#define NMAX 20000
#define KNN 6
#define KCAND 6
#define NPARTK 6
#define NSUB 4
#define CTOT (NPARTK*NSUB*KCAND)   /* 144 candidate slots per node */
#define CSLICE (CTOT/8)            /* 18 per refine thread */
#define CMERGE 48                  /* 8 slices x 6 */

typedef unsigned int u32;

// ---------------- scratch (device globals; no allocation allowed) ----------------
__device__ __align__(16) float g_cnt [NMAX];
__device__ __align__(16) float g_agg1[NMAX*16];
__device__ __align__(16) float g_x1  [NMAX*16];
__device__ __align__(16) float g_sq1 [NMAX];
__device__ __align__(16) float g_y1  [NMAX*32];
__device__ __align__(16) float g_sq2 [NMAX];
__device__ __align__(16) float g_cat0[NMAX*48];
__device__ __align__(16) float g_agg2[NMAX*48];
__device__ __align__(16) float g_x3  [NMAX*64];
__device__ __align__(16) float g_y2  [NMAX*32];
__device__ __align__(16) float g_h1  [NMAX*96];
__device__ __align__(16) int   g_ci  [NMAX*CTOT];
__device__ __align__(16) float g_md  [NMAX*CMERGE];
__device__ __align__(16) int   g_mi  [NMAX*CMERGE];

#define MMA_TF32(c0,c1,c2,c3,a0,a1,a2,a3,b0,b1) \
    asm volatile("mma.sync.aligned.m16n8k8.row.col.f32.tf32.tf32.f32 " \
        "{%0,%1,%2,%3}, {%4,%5,%6,%7}, {%8,%9}, {%0,%1,%2,%3};" \
        : "+f"(c0), "+f"(c1), "+f"(c2), "+f"(c3) \
        : "r"(a0), "r"(a1), "r"(a2), "r"(a3), "r"(b0), "r"(b1))

// float key: distance mantissa truncated to high 17 bits, j spliced into low 15.
__device__ __forceinline__ float fpack(float e, u32 j){
    return __uint_as_float((__float_as_uint(e) & 0xFFFF8000u) | j);
}
#define KEY_INIT __uint_as_float(0x7F7FFFFFu)   /* FLT_MAX: j-field 0x7FFF >= n */

// comparator: a <- min, b <- max (2x FMNMX, alu pipe, branchless)
#define CMPX(a,b) { float _lo = fminf(a,b); b = fmaxf(a,b); a = _lo; }

// Batcher odd-even mergesort network for 8 (19 comparators)
__device__ __forceinline__ void sort8(float s[8]){
    CMPX(s[0],s[1]); CMPX(s[2],s[3]); CMPX(s[4],s[5]); CMPX(s[6],s[7]);
    CMPX(s[0],s[2]); CMPX(s[1],s[3]); CMPX(s[4],s[6]); CMPX(s[5],s[7]);
    CMPX(s[1],s[2]); CMPX(s[5],s[6]);
    CMPX(s[0],s[4]); CMPX(s[1],s[5]); CMPX(s[2],s[6]); CMPX(s[3],s[7]);
    CMPX(s[2],s[4]); CMPX(s[3],s[5]);
    CMPX(s[1],s[2]); CMPX(s[3],s[4]); CMPX(s[5],s[6]);
}

// merge sorted L[6] with sorted s[8], keep lowest 6 sorted.
// s[6],s[7] cannot be in the lowest 6 of the union (7 s-elements <= them).
// t[i]=min(L[i],s[5-i]) is the bitonic-halver lower half: contains the exact
// lowest 6 and is bitonic; then bitonic-sort-6 (3 + 2x3 comparators).
__device__ __forceinline__ void merge86(float L[KCAND], const float s[8]){
    float t0 = fminf(L[0], s[5]);
    float t1 = fminf(L[1], s[4]);
    float t2 = fminf(L[2], s[3]);
    float t3 = fminf(L[3], s[2]);
    float t4 = fminf(L[4], s[1]);
    float t5 = fminf(L[5], s[0]);
    CMPX(t0,t3); CMPX(t1,t4); CMPX(t2,t5);
    CMPX(t0,t1); CMPX(t1,t2); CMPX(t0,t1);
    CMPX(t3,t4); CMPX(t4,t5); CMPX(t3,t4);
    L[0]=t0; L[1]=t1; L[2]=t2; L[3]=t3; L[4]=t4; L[5]=t5;
}

// ---------------- init: agg1 = x (self loop), cnt = 1 ----------------
__global__ void init1_kernel(const float* __restrict__ x, int n){
    int t = blockIdx.x*blockDim.x + threadIdx.x;
    if (t < n*16) g_agg1[t] = x[t];
    if (t < n)    g_cnt[t]  = 1.0f;
}

// ---------------- scatter-add of x[src] into agg1[dst], count edges ----------------
__global__ void scatter1_kernel(const int* __restrict__ src, const int* __restrict__ dst,
                                const float* __restrict__ x, int E){
    int t = blockIdx.x*blockDim.x + threadIdx.x;
    int e = t >> 2;
    if (e >= E) return;
    int q = t & 3;
    int s = src[e], d = dst[e];
    if (q == 0) atomicAdd(&g_cnt[d], 1.0f);
    float4 v = reinterpret_cast<const float4*>(x)[s*4 + q];
    float* a = &g_agg1[d*16 + q*4];
    atomicAdd(a+0, v.x); atomicAdd(a+1, v.y); atomicAdd(a+2, v.z); atomicAdd(a+3, v.w);
}

// ---------------- feast: out = relu((agg/cnt) @ W + b); optional sq + cat0 fold ----------------
template<int IN, int OUT, bool WSQ, bool CAT>
__global__ void feast_kernel(const float* __restrict__ agg, const float* __restrict__ W,
                             const float* __restrict__ b, int n,
                             float* __restrict__ out, float* __restrict__ sqout){
    __shared__ float sW[IN*OUT];
    __shared__ float sb[OUT];
    for (int t = threadIdx.x; t < IN*OUT; t += blockDim.x) sW[t] = W[t];
    for (int t = threadIdx.x; t < OUT;    t += blockDim.x) sb[t] = b[t];
    __syncthreads();
    int i = blockIdx.x*blockDim.x + threadIdx.x;
    if (i >= n) return;
    float inv = 1.0f / g_cnt[i];
    float acc[OUT];
#pragma unroll
    for (int c = 0; c < OUT; c++) acc[c] = sb[c];
    for (int d = 0; d < IN; d++){
        float v = agg[i*IN+d] * inv;
#pragma unroll
        for (int c = 0; c < OUT; c++) acc[c] = fmaf(v, sW[d*OUT+c], acc[c]);
    }
    float sq = 0.f;
#pragma unroll
    for (int c = 0; c < OUT; c++){
        float r = fmaxf(acc[c], 0.f);
        out[i*OUT+c] = r;
        if (CAT){ g_cat0[i*48+c] = r; g_agg2[i*48+c] = r; }
        sq = fmaf(r, r, sq);
    }
    if (WSQ) sqout[i] = sq;
}

// ---------------- tensor-core kNN: tf32 MMA + batch-sorted branchless selection ----------------
template<int DIM, int PAD>
__global__ void __launch_bounds__(256)
knn_mma_kernel(const float* __restrict__ X, const float* __restrict__ sq,
               int n, int chunk){
    const int KC = DIM/8;
    const int Q4 = DIM/4;
    __shared__ float bs[128*PAD];
    __shared__ float sqs[128];

    int tid = threadIdx.x;
    int w = tid >> 5;
    int lane = tid & 31;
    int g = lane & 3;
    int rsub = lane >> 2;
    int qbase = blockIdx.x*128 + w*16;
    int r0 = qbase + rsub;
    int r1 = r0 + 8;
    int p = blockIdx.y;
    int jbeg = p * chunk;
    int jend = min(n, jbeg + chunk);

    int rr0 = min(r0, n-1), rr1 = min(r1, n-1);
    u32 a0[KC], a1[KC], a2[KC], a3[KC];
#pragma unroll
    for (int kc = 0; kc < KC; kc++){
        a0[kc] = __float_as_uint(-2.0f * X[rr0*DIM + kc*8 + g]);
        a1[kc] = __float_as_uint(-2.0f * X[rr1*DIM + kc*8 + g]);
        a2[kc] = __float_as_uint(-2.0f * X[rr0*DIM + kc*8 + g + 4]);
        a3[kc] = __float_as_uint(-2.0f * X[rr1*DIM + kc*8 + g + 4]);
    }

    float LA[KCAND], LB[KCAND];
#pragma unroll
    for (int k = 0; k < KCAND; k++){ LA[k] = KEY_INIT; LB[k] = KEY_INIT; }

    for (int jt = jbeg; jt < jend; jt += 128){
        __syncthreads();
        for (int idx = tid; idx < 128*Q4; idx += 256){
            int jr = idx / Q4;
            int q = idx % Q4;
            int gj = jt + jr;
            float4 v = {0.f,0.f,0.f,0.f};
            if (gj < jend) v = reinterpret_cast<const float4*>(X)[gj*Q4 + q];
            float* row = &bs[jr*PAD];
            const int M = Q4;
            row[0*M + q] = v.x;
            row[1*M + q] = v.y;
            row[2*M + q] = v.z;
            row[3*M + q] = v.w;
        }
        for (int idx = tid; idx < 128; idx += 256)
            sqs[idx] = (jt + idx < jend) ? sq[jt + idx] : 1e30f;  // finite pad
        __syncthreads();

#pragma unroll
        for (int jg = 0; jg < 128; jg += 32){
            float SA[8], SB[8];
#pragma unroll
            for (int st = 0; st < 4; st++){
                int js = jg + st*8;
                float2 s2 = *reinterpret_cast<const float2*>(&sqs[js + 2*g]);
                float c0 = s2.x, c1 = s2.y, c2 = s2.x, c3 = s2.y;
                const float* row = &bs[(js + rsub)*PAD + g*Q4];
                if (DIM == 16){
                    float4 bf = *reinterpret_cast<const float4*>(row);
                    MMA_TF32(c0,c1,c2,c3, a0[0],a1[0],a2[0],a3[0],
                             __float_as_uint(bf.x), __float_as_uint(bf.y));
                    MMA_TF32(c0,c1,c2,c3, a0[KC-1],a1[KC-1],a2[KC-1],a3[KC-1],
                             __float_as_uint(bf.z), __float_as_uint(bf.w));
                } else {
                    float4 b1f = *reinterpret_cast<const float4*>(row);
                    float4 b2f = *reinterpret_cast<const float4*>(row + 4);
                    MMA_TF32(c0,c1,c2,c3, a0[0],a1[0],a2[0],a3[0],
                             __float_as_uint(b1f.x), __float_as_uint(b1f.y));
                    MMA_TF32(c0,c1,c2,c3, a0[1],a1[1],a2[1],a3[1],
                             __float_as_uint(b1f.z), __float_as_uint(b1f.w));
                    MMA_TF32(c0,c1,c2,c3, a0[KC-2],a1[KC-2],a2[KC-2],a3[KC-2],
                             __float_as_uint(b2f.x), __float_as_uint(b2f.y));
                    MMA_TF32(c0,c1,c2,c3, a0[KC-1],a1[KC-1],a2[KC-1],a3[KC-1],
                             __float_as_uint(b2f.z), __float_as_uint(b2f.w));
                }
                u32 j0 = (u32)(jt + js + 2*g);
                SA[st*2+0] = fpack(c0, j0);
                SA[st*2+1] = fpack(c1, j0+1);
                SB[st*2+0] = fpack(c2, j0);
                SB[st*2+1] = fpack(c3, j0+1);
            }
            sort8(SA); merge86(LA, SA);
            sort8(SB); merge86(LB, SB);
        }
    }
    if (r0 < n){
        int base = r0*CTOT + (p*NSUB + g)*KCAND;
#pragma unroll
        for (int k = 0; k < KCAND; k++) g_ci[base+k] = (int)(__float_as_uint(LA[k]) & 0x7FFFu);
    }
    if (r1 < n){
        int base = r1*CTOT + (p*NSUB + g)*KCAND;
#pragma unroll
        for (int k = 0; k < KCAND; k++) g_ci[base+k] = (int)(__float_as_uint(LB[k]) & 0x7FFFu);
    }
}

// ---------------- refine stage A: exact fp32 recompute, 8 threads/node ----------------
template<int DIM>
__global__ void refineA_kernel(const float* __restrict__ X, const float* __restrict__ sq,
                               int n){
    const int Q4 = DIM/4;
    int t = blockIdx.x*blockDim.x + threadIdx.x;
    int i = t >> 3;
    int s = t & 7;
    if (i >= n) return;
    float4 xi[Q4];
#pragma unroll
    for (int q = 0; q < Q4; q++) xi[q] = reinterpret_cast<const float4*>(X)[i*Q4 + q];

    float bd[KNN]; unsigned bi[KNN];
#pragma unroll
    for (int k = 0; k < KNN; k++){ bd[k] = INFINITY; bi[k] = 0xFFFFFFFFu; }

    int base = i*CTOT + s*CSLICE;
    for (int c = 0; c < CSLICE; c++){
        int jraw = g_ci[base+c];
        if (jraw >= n || jraw == i) continue;
        unsigned j = (unsigned)jraw;
        float dot = 0.f;
#pragma unroll
        for (int q = 0; q < Q4; q++){
            float4 xj = reinterpret_cast<const float4*>(X)[jraw*Q4 + q];
            dot = fmaf(xi[q].x, xj.x, dot);
            dot = fmaf(xi[q].y, xj.y, dot);
            dot = fmaf(xi[q].z, xj.z, dot);
            dot = fmaf(xi[q].w, xj.w, dot);
        }
        float e = fmaf(-2.f, dot, sq[jraw]);
        if (e < bd[KNN-1] || (e == bd[KNN-1] && j < bi[KNN-1])){
            bd[KNN-1] = e; bi[KNN-1] = j;
#pragma unroll
            for (int k = KNN-1; k > 0; k--){
                bool sw = (bd[k] < bd[k-1]) || (bd[k] == bd[k-1] && bi[k] < bi[k-1]);
                if (sw){
                    float td = bd[k]; bd[k] = bd[k-1]; bd[k-1] = td;
                    unsigned ti = bi[k]; bi[k] = bi[k-1]; bi[k-1] = ti;
                }
            }
        }
    }
    int ob = i*CMERGE + s*KNN;
#pragma unroll
    for (int k = 0; k < KNN; k++){ g_md[ob+k] = bd[k]; g_mi[ob+k] = (int)bi[k]; }
}

// ---------------- dynamic edge conv (with fused candidate merge; optional cat0 fold) ----------------
template<int F, bool CAT>
__global__ void edgeconv_kernel(const float* __restrict__ X,
                                const float* __restrict__ W1, const float* __restrict__ b1,
                                const float* __restrict__ W2, const float* __restrict__ b2,
                                int n, float* __restrict__ Y, float* __restrict__ sqout){
    __shared__ float sW1[2*F*32];
    __shared__ float sb1[32];
    __shared__ float sW2[32*32];
    __shared__ float sb2[32];
    for (int t = threadIdx.x; t < 2*F*32; t += blockDim.x) sW1[t] = W1[t];
    for (int t = threadIdx.x; t < 32*32;  t += blockDim.x) sW2[t] = W2[t];
    if (threadIdx.x < 32){ sb1[threadIdx.x] = b1[threadIdx.x]; sb2[threadIdx.x] = b2[threadIdx.x]; }
    __syncthreads();
    int i = blockIdx.x*blockDim.x + threadIdx.x;
    if (i >= n) return;

    // fused refineB: merge 48 exact (dist, idx) candidates -> top-6
    float bd[KNN]; unsigned bi[KNN];
#pragma unroll
    for (int k = 0; k < KNN; k++){ bd[k] = INFINITY; bi[k] = 0xFFFFFFFFu; }
    int mbase = i*CMERGE;
    for (int c = 0; c < CMERGE; c++){
        float d = g_md[mbase+c];
        unsigned j = (unsigned)g_mi[mbase+c];
        if (j == 0xFFFFFFFFu) continue;
        if (d < bd[KNN-1] || (d == bd[KNN-1] && j < bi[KNN-1])){
            bd[KNN-1] = d; bi[KNN-1] = j;
#pragma unroll
            for (int k = KNN-1; k > 0; k--){
                bool sw = (bd[k] < bd[k-1]) || (bd[k] == bd[k-1] && bi[k] < bi[k-1]);
                if (sw){
                    float td = bd[k]; bd[k] = bd[k-1]; bd[k-1] = td;
                    unsigned ti = bi[k]; bi[k] = bi[k-1]; bi[k-1] = ti;
                }
            }
        }
    }

    float base[32];
#pragma unroll
    for (int c = 0; c < 32; c++) base[c] = sb1[c];
    for (int d = 0; d < F; d++){
        float v = X[i*F+d];
#pragma unroll
        for (int c = 0; c < 32; c++) base[c] = fmaf(v, sW1[d*32+c], base[c]);
    }
    float acc[32];
#pragma unroll
    for (int c = 0; c < 32; c++) acc[c] = -INFINITY;

    for (int kk = 0; kk < KNN; kk++){
        int j = (int)bi[kk];
        float h[32];
#pragma unroll
        for (int c = 0; c < 32; c++) h[c] = base[c];
        for (int d = 0; d < F; d++){
            float v = X[j*F+d] - X[i*F+d];
#pragma unroll
            for (int c = 0; c < 32; c++) h[c] = fmaf(v, sW1[(F+d)*32+c], h[c]);
        }
#pragma unroll
        for (int c = 0; c < 32; c++) h[c] = fmaxf(h[c], 0.f);
#pragma unroll
        for (int c = 0; c < 32; c++){
            float o = sb2[c];
#pragma unroll
            for (int k = 0; k < 32; k++) o = fmaf(h[k], sW2[k*32+c], o);
            acc[c] = fmaxf(acc[c], o);
        }
    }
    float sqv = 0.f;
#pragma unroll
    for (int c = 0; c < 32; c++){
        float r = fmaxf(acc[c], 0.f);
        Y[i*32+c] = r;
        if (CAT){ g_cat0[i*48+16+c] = r; g_agg2[i*48+16+c] = r; }
        sqv = fmaf(r, r, sqv);
    }
    if (sqout) sqout[i] = sqv;
}

__global__ void scatter2_kernel(const int* __restrict__ src, const int* __restrict__ dst, int E){
    int t = blockIdx.x*blockDim.x + threadIdx.x;
    int e = t / 12;
    if (e >= E) return;
    int q = t % 12;
    int s = src[e], d = dst[e];
    float4 v = reinterpret_cast<const float4*>(g_cat0)[s*12 + q];
    float* a = &g_agg2[d*48 + q*4];
    atomicAdd(a+0, v.x); atomicAdd(a+1, v.y); atomicAdd(a+2, v.z); atomicAdd(a+3, v.w);
}

// ---------------- MLP layer 1 ----------------
__global__ void mlp1_kernel(const float* __restrict__ W, const float* __restrict__ b, int n){
    __shared__ float sW[96*96];
    __shared__ float sb[96];
    for (int t = threadIdx.x; t < 96*96; t += blockDim.x) sW[t] = W[t];
    for (int t = threadIdx.x; t < 96;    t += blockDim.x) sb[t] = b[t];
    __syncthreads();
    int i = blockIdx.x*blockDim.x + threadIdx.x;
    if (i >= n) return;
    float acc[96];
#pragma unroll
    for (int c = 0; c < 96; c++) acc[c] = sb[c];
    for (int d = 0; d < 64; d++){
        float v = g_x3[i*64+d];
#pragma unroll
        for (int c = 0; c < 96; c++) acc[c] = fmaf(v, sW[d*96+c], acc[c]);
    }
    for (int d = 0; d < 32; d++){
        float v = g_y2[i*32+d];
#pragma unroll
        for (int c = 0; c < 96; c++) acc[c] = fmaf(v, sW[(64+d)*96+c], acc[c]);
    }
#pragma unroll
    for (int c = 0; c < 96; c++) g_h1[i*96+c] = fmaxf(acc[c], 0.f);
}

// ---------------- MLP layers 2..out ----------------
__global__ void mlp2_kernel(const float* __restrict__ W2, const float* __restrict__ b2,
                            const float* __restrict__ W3, const float* __restrict__ b3,
                            const float* __restrict__ Wo, const float* __restrict__ bo,
                            int n, float* __restrict__ out){
    __shared__ float sW2[96*32]; __shared__ float sb2v[32];
    __shared__ float sW3[32*8];  __shared__ float sb3v[8];
    __shared__ float sWo[8];     __shared__ float sbo;
    for (int t = threadIdx.x; t < 96*32; t += blockDim.x) sW2[t] = W2[t];
    for (int t = threadIdx.x; t < 32*8;  t += blockDim.x) sW3[t] = W3[t];
    if (threadIdx.x < 32) sb2v[threadIdx.x] = b2[threadIdx.x];
    if (threadIdx.x < 8){ sb3v[threadIdx.x] = b3[threadIdx.x]; sWo[threadIdx.x] = Wo[threadIdx.x]; }
    if (threadIdx.x == 0) sbo = bo[0];
    __syncthreads();
    int i = blockIdx.x*blockDim.x + threadIdx.x;
    if (i >= n) return;
    float h[32];
#pragma unroll
    for (int c = 0; c < 32; c++) h[c] = sb2v[c];
    for (int d = 0; d < 96; d++){
        float v = g_h1[i*96+d];
#pragma unroll
        for (int c = 0; c < 32; c++) h[c] = fmaf(v, sW2[d*32+c], h[c]);
    }
#pragma unroll
    for (int c = 0; c < 32; c++) h[c] = fmaxf(h[c], 0.f);
    float g[8];
#pragma unroll
    for (int c = 0; c < 8; c++){
        float o = sb3v[c];
#pragma unroll
        for (int k = 0; k < 32; k++) o = fmaf(h[k], sW3[k*8+c], o);
        g[c] = fmaxf(o, 0.f);
    }
    float z = sbo;
#pragma unroll
    for (int c = 0; c < 8; c++) z = fmaf(g[c], sWo[c], z);
    out[i] = 1.0f / (1.0f + expf(-z));
}

// ---------------- launch ----------------
extern "C" void kernel_launch(void* const* d_in, const int* in_sizes, int n_in,
                              void* d_out, int out_size){
    const float* x   = (const float*)d_in[0];
    const int*   ei  = (const int*)  d_in[1];
    int n = in_sizes[0] / 16;
    int E = in_sizes[1] / 2;
    const int* src = ei;
    const int* dst = ei + E;

    const float* cW1 = (const float*)d_in[2];
    const float* cb1 = (const float*)d_in[5];
    const float* cW3 = (const float*)d_in[6];
    const float* cb3 = (const float*)d_in[9];
    const float* e1W1=(const float*)d_in[10]; const float* e1b1=(const float*)d_in[11];
    const float* e1W2=(const float*)d_in[12]; const float* e1b2=(const float*)d_in[13];
    const float* e2W1=(const float*)d_in[14]; const float* e2b1=(const float*)d_in[15];
    const float* e2W2=(const float*)d_in[16]; const float* e2b2=(const float*)d_in[17];
    const float* l1W =(const float*)d_in[18]; const float* l1b =(const float*)d_in[19];
    const float* l2W =(const float*)d_in[20]; const float* l2b =(const float*)d_in[21];
    const float* l3W =(const float*)d_in[22]; const float* l3b =(const float*)d_in[23];
    const float* oW  =(const float*)d_in[24]; const float* ob  =(const float*)d_in[25];
    float* out = (float*)d_out;

    void *p_agg1, *p_x1, *p_sq1, *p_y1, *p_sq2, *p_agg2, *p_x3, *p_y2;
    cudaGetSymbolAddress(&p_agg1, g_agg1);
    cudaGetSymbolAddress(&p_x1,   g_x1);
    cudaGetSymbolAddress(&p_sq1,  g_sq1);
    cudaGetSymbolAddress(&p_y1,   g_y1);
    cudaGetSymbolAddress(&p_sq2,  g_sq2);
    cudaGetSymbolAddress(&p_agg2, g_agg2);
    cudaGetSymbolAddress(&p_x3,   g_x3);
    cudaGetSymbolAddress(&p_y2,   g_y2);

    int nb = (n + 127) / 128;
    int chunk = (n + NPARTK - 1) / NPARTK;
    dim3 knngrid(nb, NPARTK);
    int refA = (n*8 + 127) / 128;

    // FeaSt 1 (heads=1 => attention == 1 => segment-mean then GEMM); x1 also folded into cat0/agg2
    init1_kernel<<<(n*16 + 255)/256, 256>>>(x, n);
    scatter1_kernel<<<(E*4 + 255)/256, 256>>>(src, dst, x, E);
    feast_kernel<16,16,true,true><<<nb,128>>>((const float*)p_agg1, cW1, cb1, n,
                                              (float*)p_x1, (float*)p_sq1);
    // kNN on x1: tf32 MMA + batch-sorted selection + exact refine; merge fused into edgeconv
    knn_mma_kernel<16,16><<<knngrid,256>>>((const float*)p_x1, (const float*)p_sq1, n, chunk);
    refineA_kernel<16><<<refA,128>>>((const float*)p_x1, (const float*)p_sq1, n);
    edgeconv_kernel<16,true><<<nb,128>>>((const float*)p_x1,
                                         e1W1, e1b1, e1W2, e1b2, n,
                                         (float*)p_y1, (float*)p_sq2);
    // FeaSt 2 on cat0 = [x1|y1] (cat0/agg2 already populated by the fused epilogues)
    scatter2_kernel<<<(E*12 + 255)/256, 256>>>(src, dst, E);
    feast_kernel<48,64,false,false><<<nb,128>>>((const float*)p_agg2, cW3, cb3, n,
                                                (float*)p_x3, nullptr);
    // kNN on y1
    knn_mma_kernel<32,36><<<knngrid,256>>>((const float*)p_y1, (const float*)p_sq2, n, chunk);
    refineA_kernel<32><<<refA,128>>>((const float*)p_y1, (const float*)p_sq2, n);
    edgeconv_kernel<32,false><<<nb,128>>>((const float*)p_y1,
                                          e2W1, e2b1, e2W2, e2b2, n,
                                          (float*)p_y2, nullptr);
    // Final MLP
    mlp1_kernel<<<nb,128>>>(l1W, l1b, n);
    mlp2_kernel<<<nb,128>>>(l2W, l2b, l3W, l3b, oW, ob, n, out);
}

// round 13
// speedup vs baseline: 1.6909x; 1.0558x over previous
#include <cuda_runtime.h>
#include <math.h>

#define NMAX 20000
#define NPAD 20736                 /* NPARTK * chunk(=27*128) */
#define KNN 6
#define KCAND 6
#define NPARTK 6
#define NSUB 4
#define CTOT (NPARTK*NSUB*KCAND)   /* 144 candidate slots per node */
#define CSLICE (CTOT/8)            /* 18 per refine thread */
#define CMERGE 48                  /* 8 slices x 6 */

typedef unsigned int u32;

// ---------------- scratch (device globals; no allocation allowed) ----------------
__device__ __align__(16) float g_cnt [NMAX];
__device__ __align__(16) float g_agg1[NMAX*16];
__device__ __align__(16) float g_x1  [NMAX*16];
__device__ __align__(16) float g_x1t [NPAD*16];
__device__ __align__(16) float g_sq1 [NPAD];
__device__ __align__(16) float g_y1  [NMAX*32];
__device__ __align__(16) float g_y1t [NPAD*32];
__device__ __align__(16) float g_sq2 [NPAD];
__device__ __align__(16) float g_cat0[NMAX*48];
__device__ __align__(16) float g_agg2[NMAX*48];
__device__ __align__(16) float g_x3  [NMAX*64];
__device__ __align__(16) float g_y2  [NMAX*32];
__device__ __align__(16) float g_h1  [NMAX*96];
__device__ __align__(16) int   g_ci  [NMAX*CTOT];
__device__ __align__(16) float g_md  [NMAX*CMERGE];
__device__ __align__(16) int   g_mi  [NMAX*CMERGE];

#define MMA_TF32(c0,c1,c2,c3,a0,a1,a2,a3,b0,b1) \
    asm volatile("mma.sync.aligned.m16n8k8.row.col.f32.tf32.tf32.f32 " \
        "{%0,%1,%2,%3}, {%4,%5,%6,%7}, {%8,%9}, {%0,%1,%2,%3};" \
        : "+f"(c0), "+f"(c1), "+f"(c2), "+f"(c3) \
        : "r"(a0), "r"(a1), "r"(a2), "r"(a3), "r"(b0), "r"(b1))

// cp.async helpers (LDGSTS)
__device__ __forceinline__ void cpa16(u32 dst, const void* src){
    asm volatile("cp.async.cg.shared.global [%0], [%1], 16;" :: "r"(dst), "l"(src));
}
#define CPA_COMMIT() asm volatile("cp.async.commit_group;")
#define CPA_WAIT1()  asm volatile("cp.async.wait_group 1;")
#define CPA_WAIT0()  asm volatile("cp.async.wait_group 0;")

// float key: distance mantissa truncated to high 17 bits, j spliced into low 15.
__device__ __forceinline__ float fpack(float e, u32 j){
    return __uint_as_float((__float_as_uint(e) & 0xFFFF8000u) | j);
}
#define KEY_INIT __uint_as_float(0x7F7FFFFFu)

#define CMPX(a,b) { float _lo = fminf(a,b); b = fmaxf(a,b); a = _lo; }

// Batcher odd-even mergesort network for 8 (19 comparators)
__device__ __forceinline__ void sort8(float s[8]){
    CMPX(s[0],s[1]); CMPX(s[2],s[3]); CMPX(s[4],s[5]); CMPX(s[6],s[7]);
    CMPX(s[0],s[2]); CMPX(s[1],s[3]); CMPX(s[4],s[6]); CMPX(s[5],s[7]);
    CMPX(s[1],s[2]); CMPX(s[5],s[6]);
    CMPX(s[0],s[4]); CMPX(s[1],s[5]); CMPX(s[2],s[6]); CMPX(s[3],s[7]);
    CMPX(s[2],s[4]); CMPX(s[3],s[5]);
    CMPX(s[1],s[2]); CMPX(s[3],s[4]); CMPX(s[5],s[6]);
}

// merge sorted L[6] with sorted s[8], keep lowest 6 sorted (bitonic halver).
__device__ __forceinline__ void merge86(float L[KCAND], const float s[8]){
    float t0 = fminf(L[0], s[5]);
    float t1 = fminf(L[1], s[4]);
    float t2 = fminf(L[2], s[3]);
    float t3 = fminf(L[3], s[2]);
    float t4 = fminf(L[4], s[1]);
    float t5 = fminf(L[5], s[0]);
    CMPX(t0,t3); CMPX(t1,t4); CMPX(t2,t5);
    CMPX(t0,t1); CMPX(t1,t2); CMPX(t0,t1);
    CMPX(t3,t4); CMPX(t4,t5); CMPX(t3,t4);
    L[0]=t0; L[1]=t1; L[2]=t2; L[3]=t3; L[4]=t4; L[5]=t5;
}

// ---------------- init: agg1 = x (self loop), cnt = 1 ----------------
__global__ void init1_kernel(const float* __restrict__ x, int n){
    int t = blockIdx.x*blockDim.x + threadIdx.x;
    if (t < n*16) g_agg1[t] = x[t];
    if (t < n)    g_cnt[t]  = 1.0f;
}

// ---------------- scatter-add of x[src] into agg1[dst], count edges ----------------
__global__ void scatter1_kernel(const int* __restrict__ src, const int* __restrict__ dst,
                                const float* __restrict__ x, int E){
    int t = blockIdx.x*blockDim.x + threadIdx.x;
    int e = t >> 2;
    if (e >= E) return;
    int q = t & 3;
    int s = src[e], d = dst[e];
    if (q == 0) atomicAdd(&g_cnt[d], 1.0f);
    float4 v = reinterpret_cast<const float4*>(x)[s*4 + q];
    float* a = &g_agg1[d*16 + q*4];
    atomicAdd(a+0, v.x); atomicAdd(a+1, v.y); atomicAdd(a+2, v.z); atomicAdd(a+3, v.w);
}

// ---------------- feast: out = relu((agg/cnt) @ W + b); optional sq + cat0 fold ----------------
template<int IN, int OUT, bool WSQ, bool CAT>
__global__ void feast_kernel(const float* __restrict__ agg, const float* __restrict__ W,
                             const float* __restrict__ b, int n,
                             float* __restrict__ out, float* __restrict__ sqout){
    __shared__ float sW[IN*OUT];
    __shared__ float sb[OUT];
    for (int t = threadIdx.x; t < IN*OUT; t += blockDim.x) sW[t] = W[t];
    for (int t = threadIdx.x; t < OUT;    t += blockDim.x) sb[t] = b[t];
    __syncthreads();
    int i = blockIdx.x*blockDim.x + threadIdx.x;
    if (i >= n) return;
    float inv = 1.0f / g_cnt[i];
    float acc[OUT];
#pragma unroll
    for (int c = 0; c < OUT; c++) acc[c] = sb[c];
    for (int d = 0; d < IN; d++){
        float v = agg[i*IN+d] * inv;
#pragma unroll
        for (int c = 0; c < OUT; c++) acc[c] = fmaf(v, sW[d*OUT+c], acc[c]);
    }
    float sq = 0.f;
#pragma unroll
    for (int c = 0; c < OUT; c++){
        float r = fmaxf(acc[c], 0.f);
        out[i*OUT+c] = r;
        if (CAT){ g_cat0[i*48+c] = r; g_agg2[i*48+c] = r; }
        sq = fmaf(r, r, sq);
    }
    if (WSQ) sqout[i] = sq;
}

// ---------------- transpose X to fragment layout + pad rows/sq ----------------
// Xt[i*DIM + (e&3)*(DIM/4) + (e>>2)] = X[i*DIM + e]; pad rows (i>=n) = 0; sq pad = 1e30.
template<int DIM>
__global__ void xpose_kernel(const float* __restrict__ X, float* __restrict__ Xt,
                             float* __restrict__ sqp, int n, int npad){
    int t = blockIdx.x*blockDim.x + threadIdx.x;
    if (t >= npad*DIM) return;
    int i = t / DIM, e = t - i*DIM;
    float v = (i < n) ? X[t] : 0.f;
    Xt[i*DIM + (e&3)*(DIM/4) + (e>>2)] = v;
    if (e == 0 && i >= n) sqp[i] = 1e30f;
}

// ---------------- tensor-core kNN: cp.async double-buffered, tf32 MMA, sorted selection ----------------
template<int DIM, int PAD>
__global__ void __launch_bounds__(256,4)
knn_mma_kernel(const float* __restrict__ Xt, const float* __restrict__ sq,
               int n, int chunk){
    const int KC = DIM/8;
    const int Q4 = DIM/4;
    __shared__ float bs[2][128*PAD];
    __shared__ float sqs[2][128];

    int tid = threadIdx.x;
    int w = tid >> 5;
    int lane = tid & 31;
    int g = lane & 3;
    int rsub = lane >> 2;
    int qbase = blockIdx.x*128 + w*16;
    int r0 = qbase + rsub;
    int r1 = r0 + 8;
    int p = blockIdx.y;
    int jbeg = p * chunk;
    int T = chunk >> 7;            // full 128-tiles, guaranteed

    // A fragments from transposed layout: elem (8kc+g) at slot g*Q4+2kc (contiguous float2)
    int rr0 = min(r0, n-1), rr1 = min(r1, n-1);
    u32 a0[KC], a1[KC], a2[KC], a3[KC];
    {
        const float2* xa = (const float2*)(Xt + (size_t)rr0*DIM) + g*(Q4/2);
        const float2* xb = (const float2*)(Xt + (size_t)rr1*DIM) + g*(Q4/2);
#pragma unroll
        for (int kc = 0; kc < KC; kc++){
            float2 va = xa[kc], vb = xb[kc];
            a0[kc] = __float_as_uint(-2.0f * va.x);
            a2[kc] = __float_as_uint(-2.0f * va.y);
            a1[kc] = __float_as_uint(-2.0f * vb.x);
            a3[kc] = __float_as_uint(-2.0f * vb.y);
        }
    }

    u32 sb0 = (u32)__cvta_generic_to_shared(&bs[0][0]);
    u32 sb1 = (u32)__cvta_generic_to_shared(&bs[1][0]);
    u32 sq0 = (u32)__cvta_generic_to_shared(&sqs[0][0]);
    u32 sq1 = (u32)__cvta_generic_to_shared(&sqs[1][0]);

    float LA[KCAND], LB[KCAND];
#pragma unroll
    for (int k = 0; k < KCAND; k++){ LA[k] = KEY_INIT; LB[k] = KEY_INIT; }

    // stage helper (expanded inline): copies tile at jt into buffer b (0/1)
    #define STAGE(BUF, JT) { \
        u32 _bb = (BUF) ? sb1 : sb0; \
        u32 _bq = (BUF) ? sq1 : sq0; \
        _Pragma("unroll") \
        for (int idx = tid; idx < 128*Q4; idx += 256){ \
            int jr = idx / Q4, q = idx - jr*Q4; \
            cpa16(_bb + (u32)(jr*PAD + q*4)*4u, Xt + (size_t)((JT)+jr)*DIM + q*4); \
        } \
        if (tid < 32) cpa16(_bq + tid*16u, sq + (JT) + tid*4); \
    }

    STAGE(0, jbeg);
    CPA_COMMIT();

    for (int t = 0; t < T; t++){
        int cur = t & 1;
        if (t + 1 < T){
            STAGE(1-cur, jbeg + (t+1)*128);
            CPA_COMMIT();
            CPA_WAIT1();
        } else {
            CPA_WAIT0();
        }
        __syncthreads();

        const float* bsc = &bs[cur][0];
        const float* sqc = &sqs[cur][0];
        int jt = jbeg + t*128;

#pragma unroll
        for (int jg = 0; jg < 128; jg += 32){
            float SA[8], SB[8];
#pragma unroll
            for (int st = 0; st < 4; st++){
                int js = jg + st*8;
                float2 s2 = *reinterpret_cast<const float2*>(&sqc[js + 2*g]);
                float c0 = s2.x, c1 = s2.y, c2 = s2.x, c3 = s2.y;
                const float* row = &bsc[(js + rsub)*PAD + g*Q4];
                if (DIM == 16){
                    float4 bf = *reinterpret_cast<const float4*>(row);
                    MMA_TF32(c0,c1,c2,c3, a0[0],a1[0],a2[0],a3[0],
                             __float_as_uint(bf.x), __float_as_uint(bf.y));
                    MMA_TF32(c0,c1,c2,c3, a0[KC-1],a1[KC-1],a2[KC-1],a3[KC-1],
                             __float_as_uint(bf.z), __float_as_uint(bf.w));
                } else {
                    float4 b1f = *reinterpret_cast<const float4*>(row);
                    float4 b2f = *reinterpret_cast<const float4*>(row + 4);
                    MMA_TF32(c0,c1,c2,c3, a0[0],a1[0],a2[0],a3[0],
                             __float_as_uint(b1f.x), __float_as_uint(b1f.y));
                    MMA_TF32(c0,c1,c2,c3, a0[1],a1[1],a2[1],a3[1],
                             __float_as_uint(b1f.z), __float_as_uint(b1f.w));
                    MMA_TF32(c0,c1,c2,c3, a0[KC-2],a1[KC-2],a2[KC-2],a3[KC-2],
                             __float_as_uint(b2f.x), __float_as_uint(b2f.y));
                    MMA_TF32(c0,c1,c2,c3, a0[KC-1],a1[KC-1],a2[KC-1],a3[KC-1],
                             __float_as_uint(b2f.z), __float_as_uint(b2f.w));
                }
                u32 j0 = (u32)(jt + js + 2*g);
                SA[st*2+0] = fpack(c0, j0);
                SA[st*2+1] = fpack(c1, j0+1);
                SB[st*2+0] = fpack(c2, j0);
                SB[st*2+1] = fpack(c3, j0+1);
            }
            sort8(SA); merge86(LA, SA);
            sort8(SB); merge86(LB, SB);
        }
        __syncthreads();
    }
    #undef STAGE

    if (r0 < n){
        int base = r0*CTOT + (p*NSUB + g)*KCAND;
#pragma unroll
        for (int k = 0; k < KCAND; k++) g_ci[base+k] = (int)(__float_as_uint(LA[k]) & 0x7FFFu);
    }
    if (r1 < n){
        int base = r1*CTOT + (p*NSUB + g)*KCAND;
#pragma unroll
        for (int k = 0; k < KCAND; k++) g_ci[base+k] = (int)(__float_as_uint(LB[k]) & 0x7FFFu);
    }
}

// ---------------- refine stage A: exact fp32 recompute, 8 threads/node ----------------
template<int DIM>
__global__ void refineA_kernel(const float* __restrict__ X, const float* __restrict__ sq,
                               int n){
    const int Q4 = DIM/4;
    int t = blockIdx.x*blockDim.x + threadIdx.x;
    int i = t >> 3;
    int s = t & 7;
    if (i >= n) return;
    float4 xi[Q4];
#pragma unroll
    for (int q = 0; q < Q4; q++) xi[q] = reinterpret_cast<const float4*>(X)[i*Q4 + q];

    float bd[KNN]; unsigned bi[KNN];
#pragma unroll
    for (int k = 0; k < KNN; k++){ bd[k] = INFINITY; bi[k] = 0xFFFFFFFFu; }

    int base = i*CTOT + s*CSLICE;
    for (int c = 0; c < CSLICE; c++){
        int jraw = g_ci[base+c];
        if (jraw >= n || jraw == i) continue;
        unsigned j = (unsigned)jraw;
        float dot = 0.f;
#pragma unroll
        for (int q = 0; q < Q4; q++){
            float4 xj = reinterpret_cast<const float4*>(X)[jraw*Q4 + q];
            dot = fmaf(xi[q].x, xj.x, dot);
            dot = fmaf(xi[q].y, xj.y, dot);
            dot = fmaf(xi[q].z, xj.z, dot);
            dot = fmaf(xi[q].w, xj.w, dot);
        }
        float e = fmaf(-2.f, dot, sq[jraw]);
        if (e < bd[KNN-1] || (e == bd[KNN-1] && j < bi[KNN-1])){
            bd[KNN-1] = e; bi[KNN-1] = j;
#pragma unroll
            for (int k = KNN-1; k > 0; k--){
                bool sw = (bd[k] < bd[k-1]) || (bd[k] == bd[k-1] && bi[k] < bi[k-1]);
                if (sw){
                    float td = bd[k]; bd[k] = bd[k-1]; bd[k-1] = td;
                    unsigned ti = bi[k]; bi[k] = bi[k-1]; bi[k-1] = ti;
                }
            }
        }
    }
    int ob = i*CMERGE + s*KNN;
#pragma unroll
    for (int k = 0; k < KNN; k++){ g_md[ob+k] = bd[k]; g_mi[ob+k] = (int)bi[k]; }
}

// ---------------- dynamic edge conv (fused candidate merge; optional cat0 fold) ----------------
template<int F, bool CAT>
__global__ void edgeconv_kernel(const float* __restrict__ X,
                                const float* __restrict__ W1, const float* __restrict__ b1,
                                const float* __restrict__ W2, const float* __restrict__ b2,
                                int n, float* __restrict__ Y, float* __restrict__ sqout){
    __shared__ float sW1[2*F*32];
    __shared__ float sb1[32];
    __shared__ float sW2[32*32];
    __shared__ float sb2[32];
    for (int t = threadIdx.x; t < 2*F*32; t += blockDim.x) sW1[t] = W1[t];
    for (int t = threadIdx.x; t < 32*32;  t += blockDim.x) sW2[t] = W2[t];
    if (threadIdx.x < 32){ sb1[threadIdx.x] = b1[threadIdx.x]; sb2[threadIdx.x] = b2[threadIdx.x]; }
    __syncthreads();
    int i = blockIdx.x*blockDim.x + threadIdx.x;
    if (i >= n) return;

    // fused refineB: merge 48 exact (dist, idx) candidates -> top-6
    float bd[KNN]; unsigned bi[KNN];
#pragma unroll
    for (int k = 0; k < KNN; k++){ bd[k] = INFINITY; bi[k] = 0xFFFFFFFFu; }
    int mbase = i*CMERGE;
    for (int c = 0; c < CMERGE; c++){
        float d = g_md[mbase+c];
        unsigned j = (unsigned)g_mi[mbase+c];
        if (j == 0xFFFFFFFFu) continue;
        if (d < bd[KNN-1] || (d == bd[KNN-1] && j < bi[KNN-1])){
            bd[KNN-1] = d; bi[KNN-1] = j;
#pragma unroll
            for (int k = KNN-1; k > 0; k--){
                bool sw = (bd[k] < bd[k-1]) || (bd[k] == bd[k-1] && bi[k] < bi[k-1]);
                if (sw){
                    float td = bd[k]; bd[k] = bd[k-1]; bd[k-1] = td;
                    unsigned ti = bi[k]; bi[k] = bi[k-1]; bi[k-1] = ti;
                }
            }
        }
    }

    float base[32];
#pragma unroll
    for (int c = 0; c < 32; c++) base[c] = sb1[c];
    for (int d = 0; d < F; d++){
        float v = X[i*F+d];
#pragma unroll
        for (int c = 0; c < 32; c++) base[c] = fmaf(v, sW1[d*32+c], base[c]);
    }
    float acc[32];
#pragma unroll
    for (int c = 0; c < 32; c++) acc[c] = -INFINITY;

    for (int kk = 0; kk < KNN; kk++){
        int j = (int)bi[kk];
        float h[32];
#pragma unroll
        for (int c = 0; c < 32; c++) h[c] = base[c];
        for (int d = 0; d < F; d++){
            float v = X[j*F+d] - X[i*F+d];
#pragma unroll
            for (int c = 0; c < 32; c++) h[c] = fmaf(v, sW1[(F+d)*32+c], h[c]);
        }
#pragma unroll
        for (int c = 0; c < 32; c++) h[c] = fmaxf(h[c], 0.f);
#pragma unroll
        for (int c = 0; c < 32; c++){
            float o = sb2[c];
#pragma unroll
            for (int k = 0; k < 32; k++) o = fmaf(h[k], sW2[k*32+c], o);
            acc[c] = fmaxf(acc[c], o);
        }
    }
    float sqv = 0.f;
#pragma unroll
    for (int c = 0; c < 32; c++){
        float r = fmaxf(acc[c], 0.f);
        Y[i*32+c] = r;
        if (CAT){ g_cat0[i*48+16+c] = r; g_agg2[i*48+16+c] = r; }
        sqv = fmaf(r, r, sqv);
    }
    if (sqout) sqout[i] = sqv;
}

__global__ void scatter2_kernel(const int* __restrict__ src, const int* __restrict__ dst, int E){
    int t = blockIdx.x*blockDim.x + threadIdx.x;
    int e = t / 12;
    if (e >= E) return;
    int q = t % 12;
    int s = src[e], d = dst[e];
    float4 v = reinterpret_cast<const float4*>(g_cat0)[s*12 + q];
    float* a = &g_agg2[d*48 + q*4];
    atomicAdd(a+0, v.x); atomicAdd(a+1, v.y); atomicAdd(a+2, v.z); atomicAdd(a+3, v.w);
}

// ---------------- MLP layer 1 ----------------
__global__ void mlp1_kernel(const float* __restrict__ W, const float* __restrict__ b, int n){
    __shared__ float sW[96*96];
    __shared__ float sb[96];
    for (int t = threadIdx.x; t < 96*96; t += blockDim.x) sW[t] = W[t];
    for (int t = threadIdx.x; t < 96;    t += blockDim.x) sb[t] = b[t];
    __syncthreads();
    int i = blockIdx.x*blockDim.x + threadIdx.x;
    if (i >= n) return;
    float acc[96];
#pragma unroll
    for (int c = 0; c < 96; c++) acc[c] = sb[c];
    for (int d = 0; d < 64; d++){
        float v = g_x3[i*64+d];
#pragma unroll
        for (int c = 0; c < 96; c++) acc[c] = fmaf(v, sW[d*96+c], acc[c]);
    }
    for (int d = 0; d < 32; d++){
        float v = g_y2[i*32+d];
#pragma unroll
        for (int c = 0; c < 96; c++) acc[c] = fmaf(v, sW[(64+d)*96+c], acc[c]);
    }
#pragma unroll
    for (int c = 0; c < 96; c++) g_h1[i*96+c] = fmaxf(acc[c], 0.f);
}

// ---------------- MLP layers 2..out ----------------
__global__ void mlp2_kernel(const float* __restrict__ W2, const float* __restrict__ b2,
                            const float* __restrict__ W3, const float* __restrict__ b3,
                            const float* __restrict__ Wo, const float* __restrict__ bo,
                            int n, float* __restrict__ out){
    __shared__ float sW2[96*32]; __shared__ float sb2v[32];
    __shared__ float sW3[32*8];  __shared__ float sb3v[8];
    __shared__ float sWo[8];     __shared__ float sbo;
    for (int t = threadIdx.x; t < 96*32; t += blockDim.x) sW2[t] = W2[t];
    for (int t = threadIdx.x; t < 32*8;  t += blockDim.x) sW3[t] = W3[t];
    if (threadIdx.x < 32) sb2v[threadIdx.x] = b2[threadIdx.x];
    if (threadIdx.x < 8){ sb3v[threadIdx.x] = b3[threadIdx.x]; sWo[threadIdx.x] = Wo[threadIdx.x]; }
    if (threadIdx.x == 0) sbo = bo[0];
    __syncthreads();
    int i = blockIdx.x*blockDim.x + threadIdx.x;
    if (i >= n) return;
    float h[32];
#pragma unroll
    for (int c = 0; c < 32; c++) h[c] = sb2v[c];
    for (int d = 0; d < 96; d++){
        float v = g_h1[i*96+d];
#pragma unroll
        for (int c = 0; c < 32; c++) h[c] = fmaf(v, sW2[d*32+c], h[c]);
    }
#pragma unroll
    for (int c = 0; c < 32; c++) h[c] = fmaxf(h[c], 0.f);
    float g[8];
#pragma unroll
    for (int c = 0; c < 8; c++){
        float o = sb3v[c];
#pragma unroll
        for (int k = 0; k < 32; k++) o = fmaf(h[k], sW3[k*8+c], o);
        g[c] = fmaxf(o, 0.f);
    }
    float z = sbo;
#pragma unroll
    for (int c = 0; c < 8; c++) z = fmaf(g[c], sWo[c], z);
    out[i] = 1.0f / (1.0f + expf(-z));
}

// ---------------- launch ----------------
extern "C" void kernel_launch(void* const* d_in, const int* in_sizes, int n_in,
                              void* d_out, int out_size){
    const float* x   = (const float*)d_in[0];
    const int*   ei  = (const int*)  d_in[1];
    int n = in_sizes[0] / 16;
    int E = in_sizes[1] / 2;
    const int* src = ei;
    const int* dst = ei + E;

    const float* cW1 = (const float*)d_in[2];
    const float* cb1 = (const float*)d_in[5];
    const float* cW3 = (const float*)d_in[6];
    const float* cb3 = (const float*)d_in[9];
    const float* e1W1=(const float*)d_in[10]; const float* e1b1=(const float*)d_in[11];
    const float* e1W2=(const float*)d_in[12]; const float* e1b2=(const float*)d_in[13];
    const float* e2W1=(const float*)d_in[14]; const float* e2b1=(const float*)d_in[15];
    const float* e2W2=(const float*)d_in[16]; const float* e2b2=(const float*)d_in[17];
    const float* l1W =(const float*)d_in[18]; const float* l1b =(const float*)d_in[19];
    const float* l2W =(const float*)d_in[20]; const float* l2b =(const float*)d_in[21];
    const float* l3W =(const float*)d_in[22]; const float* l3b =(const float*)d_in[23];
    const float* oW  =(const float*)d_in[24]; const float* ob  =(const float*)d_in[25];
    float* out = (float*)d_out;

    void *p_agg1, *p_x1, *p_x1t, *p_sq1, *p_y1, *p_y1t, *p_sq2, *p_agg2, *p_x3, *p_y2;
    cudaGetSymbolAddress(&p_agg1, g_agg1);
    cudaGetSymbolAddress(&p_x1,   g_x1);
    cudaGetSymbolAddress(&p_x1t,  g_x1t);
    cudaGetSymbolAddress(&p_sq1,  g_sq1);
    cudaGetSymbolAddress(&p_y1,   g_y1);
    cudaGetSymbolAddress(&p_y1t,  g_y1t);
    cudaGetSymbolAddress(&p_sq2,  g_sq2);
    cudaGetSymbolAddress(&p_agg2, g_agg2);
    cudaGetSymbolAddress(&p_x3,   g_x3);
    cudaGetSymbolAddress(&p_y2,   g_y2);

    int nb = (n + 127) / 128;
    int tilesPerPart = (n + NPARTK*128 - 1) / (NPARTK*128);
    int chunk = tilesPerPart * 128;          // 3456 for n=20000
    int npad = NPARTK * chunk;               // 20736 <= NPAD
    dim3 knngrid(nb, NPARTK);
    int refA = (n*8 + 127) / 128;

    // FeaSt 1 (heads=1 => attention == 1 => segment-mean then GEMM); x1 folded into cat0/agg2
    init1_kernel<<<(n*16 + 255)/256, 256>>>(x, n);
    scatter1_kernel<<<(E*4 + 255)/256, 256>>>(src, dst, x, E);
    feast_kernel<16,16,true,true><<<nb,128>>>((const float*)p_agg1, cW1, cb1, n,
                                              (float*)p_x1, (float*)p_sq1);
    // kNN on x1: transpose -> cp.async-pipelined tf32 MMA -> exact refine (merge fused in edgeconv)
    xpose_kernel<16><<<(npad*16 + 255)/256, 256>>>((const float*)p_x1, (float*)p_x1t,
                                                   (float*)p_sq1, n, npad);
    knn_mma_kernel<16,16><<<knngrid,256>>>((const float*)p_x1t, (const float*)p_sq1, n, chunk);
    refineA_kernel<16><<<refA,128>>>((const float*)p_x1, (const float*)p_sq1, n);
    edgeconv_kernel<16,true><<<nb,128>>>((const float*)p_x1,
                                         e1W1, e1b1, e1W2, e1b2, n,
                                         (float*)p_y1, (float*)p_sq2);
    // FeaSt 2 on cat0 = [x1|y1]
    scatter2_kernel<<<(E*12 + 255)/256, 256>>>(src, dst, E);
    feast_kernel<48,64,false,false><<<nb,128>>>((const float*)p_agg2, cW3, cb3, n,
                                                (float*)p_x3, nullptr);
    // kNN on y1
    xpose_kernel<32><<<(npad*32 + 255)/256, 256>>>((const float*)p_y1, (float*)p_y1t,
                                                   (float*)p_sq2, n, npad);
    knn_mma_kernel<32,36><<<knngrid,256>>>((const float*)p_y1t, (const float*)p_sq2, n, chunk);
    refineA_kernel<32><<<refA,128>>>((const float*)p_y1, (const float*)p_sq2, n);
    edgeconv_kernel<32,false><<<nb,128>>>((const float*)p_y1,
                                          e2W1, e2b1, e2W2, e2b2, n,
                                          (float*)p_y2, nullptr);
    // Final MLP
    mlp1_kernel<<<nb,128>>>(l1W, l1b, n);
    mlp2_kernel<<<nb,128>>>(l2W, l2b, l3W, l3b, oW, ob, n, out);
}